// round 1
// baseline (speedup 1.0000x reference)
#include <cuda_runtime.h>
#include <cuda_bf16.h>

// ---------------- problem constants ----------------
constexpr int NN  = 32768;   // nodes
constexpr int HH  = 128;     // hidden
constexpr int RR  = 16;      // rules
constexpr int OUTC = 40;     // output classes
constexpr float EPS = 1e-5f;

// ---------------- device scratch ----------------
__device__ __align__(16) float g_h[NN * HH];      // node features (running)
__device__ __align__(16) float g_msg[NN * HH];    // per-node message (rule-mixed)
__device__ __align__(16) float g_a[NN * HH];      // post-aggregation activation
__device__ float g_w[NN * RR];                    // firing strengths
__device__ int   g_deg[NN];
__device__ int   g_cursor[NN];
__device__ int   g_rowptr[NN + 1];
__device__ int   g_col[1 << 20];                  // CSR column (src) list, E = 1M
__device__ float g_sum[HH];
__device__ float g_sumsq[HH];

// ---------------- CSR build ----------------
__global__ void k_zero_csr() {
    int i = blockIdx.x * blockDim.x + threadIdx.x;
    if (i < NN) { g_deg[i] = 0; g_cursor[i] = 0; }
}

__global__ void k_count(const int* __restrict__ dst, int E) {
    int e = blockIdx.x * blockDim.x + threadIdx.x;
    if (e < E) atomicAdd(&g_deg[dst[e]], 1);
}

// single block, 1024 threads, 32 nodes each: exclusive scan -> row_ptr
__global__ void k_scan(int E) {
    __shared__ int sh[1024];
    int t = threadIdx.x;
    int cnt[32];
    int tot = 0;
    #pragma unroll
    for (int i = 0; i < 32; i++) { cnt[i] = g_deg[t * 32 + i]; tot += cnt[i]; }
    sh[t] = tot;
    __syncthreads();
    // Kogge-Stone inclusive scan over 1024 thread totals
    for (int off = 1; off < 1024; off <<= 1) {
        int v = (t >= off) ? sh[t - off] : 0;
        __syncthreads();
        sh[t] += v;
        __syncthreads();
    }
    int base = sh[t] - tot;  // exclusive prefix for this thread's chunk
    #pragma unroll
    for (int i = 0; i < 32; i++) { g_rowptr[t * 32 + i] = base; base += cnt[i]; }
    if (t == 1023) g_rowptr[NN] = E;
}

__global__ void k_fill(const int* __restrict__ src, const int* __restrict__ dst, int E) {
    int e = blockIdx.x * blockDim.x + threadIdx.x;
    if (e < E) {
        int d = dst[e];
        int p = atomicAdd(&g_cursor[d], 1);
        g_col[g_rowptr[d] + p] = src[e];
    }
}

// ---------------- tiled SGEMM (BM=BN=128, BK=16, 256 thr, 8x8 per thread) ----------------
// MODE 0: C(g_h) = relu(A(x) @ B(W_in) + bias(b_in)), K=128
// MODE 1: C(g_msg) += [w*h](synthesized A, K=2048) @ B(Wc_l); g_msg preloaded with bias term
template <int MODE>
__global__ __launch_bounds__(256, 2) void k_gemm(
    const float* __restrict__ A, const float* __restrict__ B,
    const float* __restrict__ bias, int K)
{
    __shared__ float As[16][128];
    __shared__ float Bs[16][128];
    const int tid = threadIdx.x;
    const int bm = blockIdx.x * 128;
    const int tr = (tid / 16) * 8;
    const int tc = (tid % 16) * 8;

    float acc[8][8];
    #pragma unroll
    for (int i = 0; i < 8; i++)
        #pragma unroll
        for (int j = 0; j < 8; j++) acc[i][j] = 0.f;

    for (int k0 = 0; k0 < K; k0 += 16) {
        // A tile: [128 rows][16 k]; load 2 float4 per thread, store transposed
        #pragma unroll
        for (int i = 0; i < 2; i++) {
            int idx = tid + i * 256;           // 0..511
            int row = idx >> 2;                // 0..127
            int kv  = (idx & 3) * 4;           // 0,4,8,12
            int grow = bm + row;
            float4 f;
            float scl = 1.0f;
            if (MODE == 0) {
                f = *(const float4*)&A[grow * HH + (k0 + kv)];
            } else {
                f = *(const float4*)&g_h[grow * HH + ((k0 & 127) + kv)];
                scl = g_w[grow * RR + (k0 >> 7)];
            }
            As[kv + 0][row] = f.x * scl;
            As[kv + 1][row] = f.y * scl;
            As[kv + 2][row] = f.z * scl;
            As[kv + 3][row] = f.w * scl;
        }
        // B tile: [16 k][128 cols]
        #pragma unroll
        for (int i = 0; i < 2; i++) {
            int idx = tid + i * 256;
            int kr  = idx >> 5;                // 0..15
            int col = (idx & 31) * 4;          // 0..124
            *(float4*)&Bs[kr][col] = *(const float4*)&B[(k0 + kr) * HH + col];
        }
        __syncthreads();
        #pragma unroll
        for (int kk = 0; kk < 16; kk++) {
            float ar[8], br[8];
            #pragma unroll
            for (int i = 0; i < 8; i++) ar[i] = As[kk][tr + i];
            #pragma unroll
            for (int j = 0; j < 8; j++) br[j] = Bs[kk][tc + j];
            #pragma unroll
            for (int i = 0; i < 8; i++)
                #pragma unroll
                for (int j = 0; j < 8; j++) acc[i][j] += ar[i] * br[j];
        }
        __syncthreads();
    }

    #pragma unroll
    for (int i = 0; i < 8; i++) {
        int grow = bm + tr + i;
        #pragma unroll
        for (int j = 0; j < 8; j++) {
            int gcol = tc + j;
            if (MODE == 0) {
                float v = acc[i][j] + bias[gcol];
                g_h[grow * HH + gcol] = fmaxf(v, 0.f);
            } else {
                g_msg[grow * HH + gcol] += acc[i][j];
            }
        }
    }
}

// ---------------- fuzzy rule memberships + bias preload ----------------
// one warp per node, 8 nodes per 256-thread block
__global__ __launch_bounds__(256) void k_rules(
    const float* __restrict__ cen, const float* __restrict__ wid,
    const float* __restrict__ bcl)
{
    __shared__ float sc[16][128];
    __shared__ float siw[16][128];
    __shared__ float sbc[16][128];
    const int t = threadIdx.x;
    for (int i = t; i < RR * HH; i += 256) {
        ((float*)sc)[i] = cen[i];
        float w = wid[i];
        ((float*)siw)[i] = 1.f / (2.f * w * w);
        ((float*)sbc)[i] = bcl[i];
    }
    __syncthreads();

    const int warp = t >> 5, lane = t & 31;
    const int n = blockIdx.x * 8 + warp;

    float4 h4 = *(const float4*)&g_h[n * HH + lane * 4];
    float sr[16];
    #pragma unroll
    for (int r = 0; r < 16; r++) {
        float4 c  = *(const float4*)&sc[r][lane * 4];
        float4 iw = *(const float4*)&siw[r][lane * 4];
        float dx = h4.x - c.x, dy = h4.y - c.y, dz = h4.z - c.z, dw = h4.w - c.w;
        float p = dx * dx * iw.x + dy * dy * iw.y + dz * dz * iw.z + dw * dw * iw.w;
        #pragma unroll
        for (int o = 16; o; o >>= 1) p += __shfl_xor_sync(0xffffffffu, p, o);
        sr[r] = -p * (1.f / 128.f);
    }
    float m = sr[0];
    #pragma unroll
    for (int r = 1; r < 16; r++) m = fmaxf(m, sr[r]);
    float s = 0.f;
    #pragma unroll
    for (int r = 0; r < 16; r++) { sr[r] = expf(sr[r] - m); s += sr[r]; }
    float inv = 1.f / s;

    float4 acc = {0.f, 0.f, 0.f, 0.f};
    #pragma unroll
    for (int r = 0; r < 16; r++) {
        float wr = sr[r] * inv;
        if (lane == r) g_w[n * RR + r] = wr;
        float4 b = *(const float4*)&sbc[r][lane * 4];
        acc.x += wr * b.x; acc.y += wr * b.y; acc.z += wr * b.z; acc.w += wr * b.w;
    }
    *(float4*)&g_msg[n * HH + lane * 4] = acc;   // bias term; GEMM accumulates on top
}

// ---------------- edge aggregation (gather-sum via CSR) + relu(mean) ----------------
__global__ __launch_bounds__(256) void k_aggregate() {
    const int warp = threadIdx.x >> 5, lane = threadIdx.x & 31;
    const int n = blockIdx.x * 8 + warp;
    int s0 = g_rowptr[n], s1 = g_rowptr[n + 1];
    float4 acc = {0.f, 0.f, 0.f, 0.f};
    const float4* mp = (const float4*)g_msg;
    for (int j = s0; j < s1; j++) {
        int src = g_col[j];
        float4 v = mp[src * 32 + lane];
        acc.x += v.x; acc.y += v.y; acc.z += v.z; acc.w += v.w;
    }
    int d = s1 - s0;
    float invd = 1.f / (float)(d > 0 ? d : 1);
    float4 a;
    a.x = fmaxf(acc.x * invd, 0.f);
    a.y = fmaxf(acc.y * invd, 0.f);
    a.z = fmaxf(acc.z * invd, 0.f);
    a.w = fmaxf(acc.w * invd, 0.f);
    *(float4*)&g_a[n * HH + lane * 4] = a;
}

// ---------------- batchnorm ----------------
__global__ void k_zero_stats() {
    int t = threadIdx.x;
    if (t < HH) { g_sum[t] = 0.f; g_sumsq[t] = 0.f; }
}

__global__ __launch_bounds__(128) void k_bn_stats() {
    const int t = threadIdx.x;
    float s = 0.f, q = 0.f;
    for (int row = blockIdx.x; row < NN; row += gridDim.x) {
        float v = g_a[row * HH + t];
        s += v; q += v * v;
    }
    atomicAdd(&g_sum[t], s);
    atomicAdd(&g_sumsq[t], q);
}

__global__ __launch_bounds__(128) void k_bn_apply(
    const float* __restrict__ gamma, const float* __restrict__ beta)
{
    const int t = threadIdx.x;
    const float inv_n = 1.f / (float)NN;
    float mu  = g_sum[t] * inv_n;
    float var = g_sumsq[t] * inv_n - mu * mu;
    float sc = gamma[t] * rsqrtf(var + EPS);
    float bb = beta[t];
    for (int row = blockIdx.x; row < NN; row += gridDim.x) {
        int idx = row * HH + t;
        g_h[idx] += (g_a[idx] - mu) * sc + bb;
    }
}

// ---------------- head: out = softmax(h @ W_head + b_head) ----------------
__global__ __launch_bounds__(128) void k_head(
    const float* __restrict__ W, const float* __restrict__ b, float* __restrict__ out)
{
    __shared__ float hs[HH];
    __shared__ float lg[OUTC];
    __shared__ float red[2];
    const int t = threadIdx.x;
    const int n = blockIdx.x;
    hs[t] = g_h[n * HH + t];
    __syncthreads();
    if (t < OUTC) {
        float acc = b[t];
        #pragma unroll 8
        for (int k = 0; k < HH; k++) acc += hs[k] * W[k * OUTC + t];
        lg[t] = acc;
    }
    __syncthreads();
    if (t == 0) {
        float m = lg[0];
        for (int i = 1; i < OUTC; i++) m = fmaxf(m, lg[i]);
        red[0] = m;
    }
    __syncthreads();
    if (t < OUTC) lg[t] = expf(lg[t] - red[0]);
    __syncthreads();
    if (t == 0) {
        float s = 0.f;
        for (int i = 0; i < OUTC; i++) s += lg[i];
        red[1] = 1.f / s;
    }
    __syncthreads();
    if (t < OUTC) out[n * OUTC + t] = lg[t] * red[1];
}

// ---------------- launch ----------------
extern "C" void kernel_launch(void* const* d_in, const int* in_sizes, int n_in,
                              void* d_out, int out_size)
{
    const float* x      = (const float*)d_in[0];
    const int*   ei     = (const int*)d_in[1];
    const float* W_in   = (const float*)d_in[2];
    const float* b_in   = (const float*)d_in[3];
    const float* cen    = (const float*)d_in[4];
    const float* wid    = (const float*)d_in[5];
    const float* Wc     = (const float*)d_in[6];
    const float* bc     = (const float*)d_in[7];
    const float* gamma  = (const float*)d_in[8];
    const float* beta   = (const float*)d_in[9];
    const float* W_head = (const float*)d_in[10];
    const float* b_head = (const float*)d_in[11];
    float* out = (float*)d_out;

    const int E = in_sizes[1] / 2;
    const int* src = ei;
    const int* dst = ei + E;

    // CSR build
    k_zero_csr<<<(NN + 255) / 256, 256>>>();
    k_count<<<(E + 255) / 256, 256>>>(dst, E);
    k_scan<<<1, 1024>>>(E);
    k_fill<<<(E + 255) / 256, 256>>>(src, dst, E);

    // input layer: h = relu(x @ W_in + b_in)
    k_gemm<0><<<NN / 128, 256>>>(x, W_in, b_in, HH);

    for (int l = 0; l < 3; l++) {
        const float* cen_l = cen + l * RR * HH;
        const float* wid_l = wid + l * RR * HH;
        const float* Wc_l  = Wc + l * RR * HH * HH;
        const float* bc_l  = bc + l * RR * HH;
        k_rules<<<NN / 8, 256>>>(cen_l, wid_l, bc_l);
        k_gemm<1><<<NN / 128, 256>>>(nullptr, Wc_l, nullptr, RR * HH);
        k_aggregate<<<NN / 8, 256>>>();
        k_zero_stats<<<1, 128>>>();
        k_bn_stats<<<512, 128>>>();
        k_bn_apply<<<2048, 128>>>(gamma + l * HH, beta + l * HH);
    }

    k_head<<<NN, 128>>>(W_head, b_head, out);
}

// round 4
// speedup vs baseline: 1.2784x; 1.2784x over previous
#include <cuda_runtime.h>
#include <cuda_bf16.h>
#include <cstdint>

// ---------------- problem constants ----------------
constexpr int NN  = 32768;   // nodes
constexpr int HH  = 128;     // hidden
constexpr int RR  = 16;      // rules
constexpr int OUTC = 40;     // output classes
constexpr float EPS = 1e-5f;
constexpr int KTOT = RR * HH;   // 2048
constexpr int KC   = 32;        // K per pipeline chunk
constexpr int NCH  = KTOT / KC; // 64
constexpr int LDS_STRIDE = 36;  // floats per smem row (conflict-free frag loads)

// ---------------- device scratch ----------------
__device__ __align__(16) float g_h[NN * HH];          // node features (running)
__device__ __align__(16) float g_msg[NN * HH];        // per-node message
__device__ __align__(16) float g_a[NN * HH];          // post-aggregation activation
__device__ __align__(16) float g_BtHi[3 * HH * KTOT]; // Wc^T hi (tf32): [l][o][k]
__device__ __align__(16) float g_BtLo[3 * HH * KTOT]; // Wc^T lo (tf32 residual)
__device__ float g_w[NN * RR];                        // firing strengths
__device__ int   g_deg[NN];
__device__ int   g_cursor[NN];
__device__ int   g_rowptr[NN + 1];
__device__ int   g_col[1 << 20];
__device__ float g_sum[HH];
__device__ float g_sumsq[HH];

// ---------------- helpers ----------------
__device__ __forceinline__ uint32_t smem_u32(const void* p) {
    uint32_t a;
    asm("{ .reg .u64 t; cvta.to.shared.u64 t, %1; cvt.u32.u64 %0, t; }" : "=r"(a) : "l"(p));
    return a;
}
__device__ __forceinline__ uint32_t f2tf(float f) {
    uint32_t r;
    asm("cvt.rna.tf32.f32 %0, %1;" : "=r"(r) : "f"(f));
    return r;
}
__device__ __forceinline__ void cp_async16(uint32_t dst, const void* src) {
    asm volatile("cp.async.cg.shared.global [%0], [%1], 16;" :: "r"(dst), "l"(src));
}
__device__ __forceinline__ void cp_commit() {
    asm volatile("cp.async.commit_group;");
}
__device__ __forceinline__ void cp_wait0() {
    asm volatile("cp.async.wait_group 0;" ::: "memory");
}
__device__ __forceinline__ void sts_v4u(uint32_t addr, uint32_t a, uint32_t b, uint32_t c, uint32_t d) {
    asm volatile("st.shared.v4.b32 [%0], {%1, %2, %3, %4};"
        :: "r"(addr), "r"(a), "r"(b), "r"(c), "r"(d) : "memory");
}
__device__ __forceinline__ void mma_tf32(float* d, const uint32_t* a, const uint32_t* b) {
    asm volatile(
        "mma.sync.aligned.m16n8k8.row.col.f32.tf32.tf32.f32 "
        "{%0, %1, %2, %3}, {%4, %5, %6, %7}, {%8, %9}, {%0, %1, %2, %3};"
        : "+f"(d[0]), "+f"(d[1]), "+f"(d[2]), "+f"(d[3])
        : "r"(a[0]), "r"(a[1]), "r"(a[2]), "r"(a[3]), "r"(b[0]), "r"(b[1]));
}

// ---------------- CSR build ----------------
__global__ void k_zero_csr() {
    int i = blockIdx.x * blockDim.x + threadIdx.x;
    if (i < NN) { g_deg[i] = 0; g_cursor[i] = 0; }
}

__global__ void k_count(const int* __restrict__ dst, int E) {
    int e = blockIdx.x * blockDim.x + threadIdx.x;
    if (e < E) atomicAdd(&g_deg[dst[e]], 1);
}

__global__ void k_scan(int E) {
    __shared__ int sh[1024];
    int t = threadIdx.x;
    int cnt[32];
    int tot = 0;
    #pragma unroll
    for (int i = 0; i < 32; i++) { cnt[i] = g_deg[t * 32 + i]; tot += cnt[i]; }
    sh[t] = tot;
    __syncthreads();
    for (int off = 1; off < 1024; off <<= 1) {
        int v = (t >= off) ? sh[t - off] : 0;
        __syncthreads();
        sh[t] += v;
        __syncthreads();
    }
    int base = sh[t] - tot;
    #pragma unroll
    for (int i = 0; i < 32; i++) { g_rowptr[t * 32 + i] = base; base += cnt[i]; }
    if (t == 1023) g_rowptr[NN] = E;
}

__global__ void k_fill(const int* __restrict__ src, const int* __restrict__ dst, int E) {
    int e = blockIdx.x * blockDim.x + threadIdx.x;
    if (e < E) {
        int d = dst[e];
        int p = atomicAdd(&g_cursor[d], 1);
        g_col[g_rowptr[d] + p] = src[e];
    }
}

// ---------------- Wc transpose + hi/lo tf32 split ----------------
__global__ void k_transB(const float* __restrict__ Wc) {
    int idx = blockIdx.x * blockDim.x + threadIdx.x;  // 3*2048*128 total
    int l = idx >> 18;
    int rem = idx & 262143;
    int k = rem >> 7;
    int o = rem & 127;
    float v = Wc[idx];
    uint32_t hi = f2tf(v);
    uint32_t lo = f2tf(v - __uint_as_float(hi));
    size_t di = (size_t)l * 262144 + (size_t)o * KTOT + k;
    ((uint32_t*)g_BtHi)[di] = hi;
    ((uint32_t*)g_BtLo)[di] = lo;
}

// ---------------- input SGEMM (fp32): g_h = relu(x @ W_in + b_in), K=128 ----------------
__global__ __launch_bounds__(256, 2) void k_gemm_in(
    const float* __restrict__ A, const float* __restrict__ B,
    const float* __restrict__ bias)
{
    __shared__ float As[16][128];
    __shared__ float Bs[16][128];
    const int tid = threadIdx.x;
    const int bm = blockIdx.x * 128;
    const int tr = (tid / 16) * 8;
    const int tc = (tid % 16) * 8;

    float acc[8][8];
    #pragma unroll
    for (int i = 0; i < 8; i++)
        #pragma unroll
        for (int j = 0; j < 8; j++) acc[i][j] = 0.f;

    for (int k0 = 0; k0 < 128; k0 += 16) {
        #pragma unroll
        for (int i = 0; i < 2; i++) {
            int idx = tid + i * 256;
            int row = idx >> 2;
            int kv  = (idx & 3) * 4;
            float4 f = *(const float4*)&A[(bm + row) * HH + (k0 + kv)];
            As[kv + 0][row] = f.x; As[kv + 1][row] = f.y;
            As[kv + 2][row] = f.z; As[kv + 3][row] = f.w;
        }
        #pragma unroll
        for (int i = 0; i < 2; i++) {
            int idx = tid + i * 256;
            int kr  = idx >> 5;
            int col = (idx & 31) * 4;
            *(float4*)&Bs[kr][col] = *(const float4*)&B[(k0 + kr) * HH + col];
        }
        __syncthreads();
        #pragma unroll
        for (int kk = 0; kk < 16; kk++) {
            float ar[8], br[8];
            #pragma unroll
            for (int i = 0; i < 8; i++) ar[i] = As[kk][tr + i];
            #pragma unroll
            for (int j = 0; j < 8; j++) br[j] = Bs[kk][tc + j];
            #pragma unroll
            for (int i = 0; i < 8; i++)
                #pragma unroll
                for (int j = 0; j < 8; j++) acc[i][j] += ar[i] * br[j];
        }
        __syncthreads();
    }
    #pragma unroll
    for (int i = 0; i < 8; i++)
        #pragma unroll
        for (int j = 0; j < 8; j++) {
            float v = acc[i][j] + bias[tc + j];
            g_h[(bm + tr + i) * HH + (tc + j)] = fmaxf(v, 0.f);
        }
}

// ---------------- 3xTF32 mma.sync rule-mix GEMM ----------------
// g_msg[m, o] += sum_k (w[m, k>>7] * h[m, k&127]) * Wc^T[o, k],  K = 2048
// block tile 128x128, 8 warps (2m x 4n), warp tile 64x32, chunk K=32, double buffered
// per chunk: acc += Ahi*Bhi + Alo*Bhi + Ahi*Blo  (3xTF32, ~fp32 precision)
__global__ __launch_bounds__(256, 1) void k_mma(int layer) {
    extern __shared__ float sm[];
    // stage layout: Ahi[128*36] Alo[128*36] Bhi[128*36] Blo[128*36]
    const int TILE_F  = 128 * LDS_STRIDE;
    const int STAGE_F = 4 * TILE_F;
    const uint32_t smBase = smem_u32(sm);

    const float* __restrict__ BtHi = g_BtHi + (size_t)layer * (HH * KTOT);
    const float* __restrict__ BtLo = g_BtLo + (size_t)layer * (HH * KTOT);
    const int tid  = threadIdx.x;
    const int m0   = blockIdx.x * 128;
    const int warp = tid >> 5, lane = tid & 31;
    const int mwarp = warp >> 2;          // 0..1
    const int nwarp = warp & 3;           // 0..3
    const int g   = lane >> 2;            // 0..7
    const int tig = lane & 3;             // 0..3

    // per-thread fill mapping (4 iterations x (row, seg))
    const int frow = tid >> 3;            // 0..31 (+32 per iter)
    const int fseg = tid & 7;             // 0..7, 4 floats each

    float acc[4][4][4];
    #pragma unroll
    for (int mi = 0; mi < 4; mi++)
        #pragma unroll
        for (int ni = 0; ni < 4; ni++)
            #pragma unroll
            for (int v = 0; v < 4; v++) acc[mi][ni][v] = 0.f;

    float4 aRegs[4];
    float  wRegs[4];

    auto ldgA = [&](int c) {
        const int cb = (c & 3) * 32;
        const int r  = c >> 2;
        #pragma unroll
        for (int i = 0; i < 4; i++) {
            int row = frow + i * 32;
            aRegs[i] = *(const float4*)&g_h[(size_t)(m0 + row) * HH + cb + fseg * 4];
            wRegs[i] = __ldg(&g_w[(m0 + row) * RR + r]);
        }
    };
    auto stsA = [&](int stage) {
        #pragma unroll
        for (int i = 0; i < 4; i++) {
            int row = frow + i * 32;
            uint32_t base = smBase + (stage * STAGE_F + row * LDS_STRIDE + fseg * 4) * 4;
            float w = wRegs[i];
            float x0 = aRegs[i].x * w, x1 = aRegs[i].y * w;
            float x2 = aRegs[i].z * w, x3 = aRegs[i].w * w;
            uint32_t h0 = f2tf(x0), h1 = f2tf(x1), h2 = f2tf(x2), h3 = f2tf(x3);
            sts_v4u(base, h0, h1, h2, h3);
            uint32_t l0 = f2tf(x0 - __uint_as_float(h0));
            uint32_t l1 = f2tf(x1 - __uint_as_float(h1));
            uint32_t l2 = f2tf(x2 - __uint_as_float(h2));
            uint32_t l3 = f2tf(x3 - __uint_as_float(h3));
            sts_v4u(base + TILE_F * 4, l0, l1, l2, l3);
        }
    };
    auto cpB = [&](int c, int stage) {
        const int k0 = c * 32;
        #pragma unroll
        for (int i = 0; i < 4; i++) {
            int n = frow + i * 32;
            size_t gsrc = (size_t)n * KTOT + k0 + fseg * 4;
            uint32_t dst = smBase + (stage * STAGE_F + 2 * TILE_F + n * LDS_STRIDE + fseg * 4) * 4;
            cp_async16(dst, &BtHi[gsrc]);
            cp_async16(dst + TILE_F * 4, &BtLo[gsrc]);
        }
        cp_commit();
    };

    auto mmaChunk = [&](int stage) {
        const float* Ah = sm + stage * STAGE_F;
        const float* Al = Ah + TILE_F;
        const float* Bh = Ah + 2 * TILE_F;
        const float* Bl = Ah + 3 * TILE_F;
        #pragma unroll
        for (int ki = 0; ki < 4; ki++) {
            const int kk = ki * 8;
            uint32_t bh[4][2], bl[4][2];
            #pragma unroll
            for (int ni = 0; ni < 4; ni++) {
                int n = nwarp * 32 + ni * 8 + g;
                bh[ni][0] = __float_as_uint(Bh[n * LDS_STRIDE + kk + tig]);
                bh[ni][1] = __float_as_uint(Bh[n * LDS_STRIDE + kk + tig + 4]);
                bl[ni][0] = __float_as_uint(Bl[n * LDS_STRIDE + kk + tig]);
                bl[ni][1] = __float_as_uint(Bl[n * LDS_STRIDE + kk + tig + 4]);
            }
            #pragma unroll
            for (int mi = 0; mi < 4; mi++) {
                int m = mwarp * 64 + mi * 16;
                uint32_t ah[4], al[4];
                ah[0] = __float_as_uint(Ah[(m + g)     * LDS_STRIDE + kk + tig]);
                ah[1] = __float_as_uint(Ah[(m + g + 8) * LDS_STRIDE + kk + tig]);
                ah[2] = __float_as_uint(Ah[(m + g)     * LDS_STRIDE + kk + tig + 4]);
                ah[3] = __float_as_uint(Ah[(m + g + 8) * LDS_STRIDE + kk + tig + 4]);
                al[0] = __float_as_uint(Al[(m + g)     * LDS_STRIDE + kk + tig]);
                al[1] = __float_as_uint(Al[(m + g + 8) * LDS_STRIDE + kk + tig]);
                al[2] = __float_as_uint(Al[(m + g)     * LDS_STRIDE + kk + tig + 4]);
                al[3] = __float_as_uint(Al[(m + g + 8) * LDS_STRIDE + kk + tig + 4]);
                #pragma unroll
                for (int ni = 0; ni < 4; ni++) {
                    mma_tf32(acc[mi][ni], ah, bh[ni]);
                    mma_tf32(acc[mi][ni], al, bh[ni]);
                    mma_tf32(acc[mi][ni], ah, bl[ni]);
                }
            }
        }
    };

    // prologue
    ldgA(0);
    stsA(0);
    cpB(0, 0);

    for (int c = 0; c < NCH; ++c) {
        const int s = c & 1;
        cp_wait0();
        __syncthreads();
        if (c + 1 < NCH) {
            ldgA(c + 1);
            cpB(c + 1, s ^ 1);
        }
        mmaChunk(s);
        if (c + 1 < NCH) stsA(s ^ 1);
    }

    // epilogue: g_msg += acc
    #pragma unroll
    for (int mi = 0; mi < 4; mi++) {
        #pragma unroll
        for (int ni = 0; ni < 4; ni++) {
            int grow = m0 + mwarp * 64 + mi * 16 + g;
            int gcol = nwarp * 32 + ni * 8 + 2 * tig;
            float2* p = (float2*)&g_msg[(size_t)grow * HH + gcol];
            float2 v = *p;
            v.x += acc[mi][ni][0]; v.y += acc[mi][ni][1];
            *p = v;
            float2* q = (float2*)&g_msg[(size_t)(grow + 8) * HH + gcol];
            float2 u = *q;
            u.x += acc[mi][ni][2]; u.y += acc[mi][ni][3];
            *q = u;
        }
    }
}

// ---------------- fuzzy rule memberships + bias preload ----------------
__global__ __launch_bounds__(256) void k_rules(
    const float* __restrict__ cen, const float* __restrict__ wid,
    const float* __restrict__ bcl)
{
    __shared__ float sc[16][128];
    __shared__ float siw[16][128];
    __shared__ float sbc[16][128];
    const int t = threadIdx.x;
    for (int i = t; i < RR * HH; i += 256) {
        ((float*)sc)[i] = cen[i];
        float w = wid[i];
        ((float*)siw)[i] = 1.f / (2.f * w * w);
        ((float*)sbc)[i] = bcl[i];
    }
    __syncthreads();

    const int warp = t >> 5, lane = t & 31;
    const int n = blockIdx.x * 8 + warp;

    float4 h4 = *(const float4*)&g_h[n * HH + lane * 4];
    float sr[16];
    #pragma unroll
    for (int r = 0; r < 16; r++) {
        float4 c  = *(const float4*)&sc[r][lane * 4];
        float4 iw = *(const float4*)&siw[r][lane * 4];
        float dx = h4.x - c.x, dy = h4.y - c.y, dz = h4.z - c.z, dw = h4.w - c.w;
        float p = dx * dx * iw.x + dy * dy * iw.y + dz * dz * iw.z + dw * dw * iw.w;
        #pragma unroll
        for (int o = 16; o; o >>= 1) p += __shfl_xor_sync(0xffffffffu, p, o);
        sr[r] = -p * (1.f / 128.f);
    }
    float m = sr[0];
    #pragma unroll
    for (int r = 1; r < 16; r++) m = fmaxf(m, sr[r]);
    float s = 0.f;
    #pragma unroll
    for (int r = 0; r < 16; r++) { sr[r] = expf(sr[r] - m); s += sr[r]; }
    float inv = 1.f / s;

    float4 acc = {0.f, 0.f, 0.f, 0.f};
    #pragma unroll
    for (int r = 0; r < 16; r++) {
        float wr = sr[r] * inv;
        if (lane == r) g_w[n * RR + r] = wr;
        float4 b = *(const float4*)&sbc[r][lane * 4];
        acc.x += wr * b.x; acc.y += wr * b.y; acc.z += wr * b.z; acc.w += wr * b.w;
    }
    *(float4*)&g_msg[n * HH + lane * 4] = acc;   // bias term; MMA accumulates on top
}

// ---------------- edge aggregation (gather-sum via CSR) + relu(mean) ----------------
__global__ __launch_bounds__(256) void k_aggregate() {
    const int warp = threadIdx.x >> 5, lane = threadIdx.x & 31;
    const int n = blockIdx.x * 8 + warp;
    int s0 = g_rowptr[n], s1 = g_rowptr[n + 1];
    float4 acc = {0.f, 0.f, 0.f, 0.f};
    const float4* mp = (const float4*)g_msg;
    for (int j = s0; j < s1; j++) {
        int src = g_col[j];
        float4 v = mp[src * 32 + lane];
        acc.x += v.x; acc.y += v.y; acc.z += v.z; acc.w += v.w;
    }
    int d = s1 - s0;
    float invd = 1.f / (float)(d > 0 ? d : 1);
    float4 a;
    a.x = fmaxf(acc.x * invd, 0.f);
    a.y = fmaxf(acc.y * invd, 0.f);
    a.z = fmaxf(acc.z * invd, 0.f);
    a.w = fmaxf(acc.w * invd, 0.f);
    *(float4*)&g_a[n * HH + lane * 4] = a;
}

// ---------------- batchnorm ----------------
__global__ void k_zero_stats() {
    int t = threadIdx.x;
    if (t < HH) { g_sum[t] = 0.f; g_sumsq[t] = 0.f; }
}

__global__ __launch_bounds__(128) void k_bn_stats() {
    const int t = threadIdx.x;
    float s = 0.f, q = 0.f;
    for (int row = blockIdx.x; row < NN; row += gridDim.x) {
        float v = g_a[row * HH + t];
        s += v; q += v * v;
    }
    atomicAdd(&g_sum[t], s);
    atomicAdd(&g_sumsq[t], q);
}

__global__ __launch_bounds__(128) void k_bn_apply(
    const float* __restrict__ gamma, const float* __restrict__ beta)
{
    const int t = threadIdx.x;
    const float inv_n = 1.f / (float)NN;
    float mu  = g_sum[t] * inv_n;
    float var = g_sumsq[t] * inv_n - mu * mu;
    float sc = gamma[t] * rsqrtf(var + EPS);
    float bb = beta[t];
    for (int row = blockIdx.x; row < NN; row += gridDim.x) {
        int idx = row * HH + t;
        g_h[idx] += (g_a[idx] - mu) * sc + bb;
    }
}

// ---------------- head: out = softmax(h @ W_head + b_head) ----------------
__global__ __launch_bounds__(128) void k_head(
    const float* __restrict__ W, const float* __restrict__ b, float* __restrict__ out)
{
    __shared__ float hs[HH];
    __shared__ float lg[OUTC];
    __shared__ float red[2];
    const int t = threadIdx.x;
    const int n = blockIdx.x;
    hs[t] = g_h[n * HH + t];
    __syncthreads();
    if (t < OUTC) {
        float acc = b[t];
        #pragma unroll 8
        for (int k = 0; k < HH; k++) acc += hs[k] * W[k * OUTC + t];
        lg[t] = acc;
    }
    __syncthreads();
    if (t == 0) {
        float m = lg[0];
        for (int i = 1; i < OUTC; i++) m = fmaxf(m, lg[i]);
        red[0] = m;
    }
    __syncthreads();
    if (t < OUTC) lg[t] = expf(lg[t] - red[0]);
    __syncthreads();
    if (t == 0) {
        float s = 0.f;
        for (int i = 0; i < OUTC; i++) s += lg[i];
        red[1] = 1.f / s;
    }
    __syncthreads();
    if (t < OUTC) out[n * OUTC + t] = lg[t] * red[1];
}

// ---------------- launch ----------------
extern "C" void kernel_launch(void* const* d_in, const int* in_sizes, int n_in,
                              void* d_out, int out_size)
{
    const float* x      = (const float*)d_in[0];
    const int*   ei     = (const int*)d_in[1];
    const float* W_in   = (const float*)d_in[2];
    const float* b_in   = (const float*)d_in[3];
    const float* cen    = (const float*)d_in[4];
    const float* wid    = (const float*)d_in[5];
    const float* Wc     = (const float*)d_in[6];
    const float* bc     = (const float*)d_in[7];
    const float* gamma  = (const float*)d_in[8];
    const float* beta   = (const float*)d_in[9];
    const float* W_head = (const float*)d_in[10];
    const float* b_head = (const float*)d_in[11];
    float* out = (float*)d_out;

    const int E = in_sizes[1] / 2;
    const int* src = ei;
    const int* dst = ei + E;

    const int MMA_SMEM = 2 * 4 * 128 * LDS_STRIDE * 4;   // 147456 bytes
    cudaFuncSetAttribute(k_mma, cudaFuncAttributeMaxDynamicSharedMemorySize, MMA_SMEM);

    // CSR build
    k_zero_csr<<<(NN + 255) / 256, 256>>>();
    k_count<<<(E + 255) / 256, 256>>>(dst, E);
    k_scan<<<1, 1024>>>(E);
    k_fill<<<(E + 255) / 256, 256>>>(src, dst, E);

    // Wc transpose + hi/lo tf32 split
    k_transB<<<(3 * KTOT * HH) / 256, 256>>>(Wc);

    // input layer: h = relu(x @ W_in + b_in)
    k_gemm_in<<<NN / 128, 256>>>(x, W_in, b_in);

    for (int l = 0; l < 3; l++) {
        const float* cen_l = cen + l * RR * HH;
        const float* wid_l = wid + l * RR * HH;
        const float* bc_l  = bc + l * RR * HH;
        k_rules<<<NN / 8, 256>>>(cen_l, wid_l, bc_l);
        k_mma<<<NN / 128, 256, MMA_SMEM>>>(l);
        k_aggregate<<<NN / 8, 256>>>();
        k_zero_stats<<<1, 128>>>();
        k_bn_stats<<<512, 128>>>();
        k_bn_apply<<<2048, 128>>>(gamma + l * HH, beta + l * HH);
    }

    k_head<<<NN, 128>>>(W_head, b_head, out);
}

// round 5
// speedup vs baseline: 1.6883x; 1.3207x over previous
#include <cuda_runtime.h>
#include <cuda_bf16.h>
#include <cstdint>

// ---------------- problem constants ----------------
constexpr int NN  = 32768;   // nodes
constexpr int HH  = 128;     // hidden
constexpr int RR  = 16;      // rules
constexpr int OUTC = 40;     // output classes
constexpr float EPS = 1e-5f;
constexpr int KTOT = RR * HH;   // 2048
constexpr int KC   = 32;        // K per pipeline chunk
constexpr int NCH  = KTOT / KC; // 64
constexpr int AST  = 20;        // 32-bit words per 32-k row (16 data + 4 pad, conflict-free)
constexpr int TILE_W  = 128 * AST;   // words per tile
constexpr int STAGE_W = 4 * TILE_W;  // Ahi, Alo, Bhi, Blo

// ---------------- device scratch ----------------
__device__ __align__(16) float g_h[NN * HH];          // node features (running)
__device__ __align__(16) float g_msg[NN * HH];        // per-node message
__device__ __align__(16) float g_a[NN * HH];          // post-aggregation activation
__device__ __align__(16) __nv_bfloat16 g_BtHi[3 * HH * KTOT]; // Wc^T hi: [l][o][k]
__device__ __align__(16) __nv_bfloat16 g_BtLo[3 * HH * KTOT]; // Wc^T lo residual
__device__ float g_w[NN * RR];                        // firing strengths
__device__ int   g_deg[NN];
__device__ int   g_cursor[NN];
__device__ int   g_rowptr[NN + 1];
__device__ int   g_col[1 << 20];
__device__ float g_sum[HH];
__device__ float g_sumsq[HH];

// ---------------- helpers ----------------
__device__ __forceinline__ uint32_t smem_u32(const void* p) {
    uint32_t a;
    asm("{ .reg .u64 t; cvta.to.shared.u64 t, %1; cvt.u32.u64 %0, t; }" : "=r"(a) : "l"(p));
    return a;
}
__device__ __forceinline__ void cp_async16(uint32_t dst, const void* src) {
    asm volatile("cp.async.cg.shared.global [%0], [%1], 16;" :: "r"(dst), "l"(src));
}
__device__ __forceinline__ void cp_commit() {
    asm volatile("cp.async.commit_group;");
}
__device__ __forceinline__ void cp_wait0() {
    asm volatile("cp.async.wait_group 0;" ::: "memory");
}
__device__ __forceinline__ void sts_v2u(uint32_t addr, uint32_t a, uint32_t b) {
    asm volatile("st.shared.v2.b32 [%0], {%1, %2};" :: "r"(addr), "r"(a), "r"(b) : "memory");
}
__device__ __forceinline__ uint32_t pack_bf2(float a, float b) {
    __nv_bfloat162 t;
    t.x = __float2bfloat16(a);
    t.y = __float2bfloat16(b);
    return *(uint32_t*)&t;
}
__device__ __forceinline__ void mma_bf16(float* d, const uint32_t* a, const uint32_t* b) {
    asm volatile(
        "mma.sync.aligned.m16n8k16.row.col.f32.bf16.bf16.f32 "
        "{%0, %1, %2, %3}, {%4, %5, %6, %7}, {%8, %9}, {%0, %1, %2, %3};"
        : "+f"(d[0]), "+f"(d[1]), "+f"(d[2]), "+f"(d[3])
        : "r"(a[0]), "r"(a[1]), "r"(a[2]), "r"(a[3]), "r"(b[0]), "r"(b[1]));
}

// ---------------- CSR build ----------------
__global__ void k_zero_csr() {
    int i = blockIdx.x * blockDim.x + threadIdx.x;
    if (i < NN) { g_deg[i] = 0; g_cursor[i] = 0; }
}

__global__ void k_count(const int* __restrict__ dst, int E) {
    int e = blockIdx.x * blockDim.x + threadIdx.x;
    if (e < E) atomicAdd(&g_deg[dst[e]], 1);
}

__global__ void k_scan(int E) {
    __shared__ int sh[1024];
    int t = threadIdx.x;
    int cnt[32];
    int tot = 0;
    #pragma unroll
    for (int i = 0; i < 32; i++) { cnt[i] = g_deg[t * 32 + i]; tot += cnt[i]; }
    sh[t] = tot;
    __syncthreads();
    for (int off = 1; off < 1024; off <<= 1) {
        int v = (t >= off) ? sh[t - off] : 0;
        __syncthreads();
        sh[t] += v;
        __syncthreads();
    }
    int base = sh[t] - tot;
    #pragma unroll
    for (int i = 0; i < 32; i++) { g_rowptr[t * 32 + i] = base; base += cnt[i]; }
    if (t == 1023) g_rowptr[NN] = E;
}

__global__ void k_fill(const int* __restrict__ src, const int* __restrict__ dst, int E) {
    int e = blockIdx.x * blockDim.x + threadIdx.x;
    if (e < E) {
        int d = dst[e];
        int p = atomicAdd(&g_cursor[d], 1);
        g_col[g_rowptr[d] + p] = src[e];
    }
}

// ---------------- Wc transpose + hi/lo bf16 split ----------------
__global__ void k_transB(const float* __restrict__ Wc) {
    int idx = blockIdx.x * blockDim.x + threadIdx.x;  // 3*2048*128 total
    int l = idx >> 18;
    int rem = idx & 262143;
    int k = rem >> 7;
    int o = rem & 127;
    float v = Wc[idx];
    __nv_bfloat16 hi = __float2bfloat16(v);
    __nv_bfloat16 lo = __float2bfloat16(v - __bfloat162float(hi));
    size_t di = (size_t)l * 262144 + (size_t)o * KTOT + k;
    g_BtHi[di] = hi;
    g_BtLo[di] = lo;
}

// ---------------- input SGEMM (fp32): g_h = relu(x @ W_in + b_in), K=128 ----------------
__global__ __launch_bounds__(256, 2) void k_gemm_in(
    const float* __restrict__ A, const float* __restrict__ B,
    const float* __restrict__ bias)
{
    __shared__ float As[16][128];
    __shared__ float Bs[16][128];
    const int tid = threadIdx.x;
    const int bm = blockIdx.x * 128;
    const int tr = (tid / 16) * 8;
    const int tc = (tid % 16) * 8;

    float acc[8][8];
    #pragma unroll
    for (int i = 0; i < 8; i++)
        #pragma unroll
        for (int j = 0; j < 8; j++) acc[i][j] = 0.f;

    for (int k0 = 0; k0 < 128; k0 += 16) {
        #pragma unroll
        for (int i = 0; i < 2; i++) {
            int idx = tid + i * 256;
            int row = idx >> 2;
            int kv  = (idx & 3) * 4;
            float4 f = *(const float4*)&A[(bm + row) * HH + (k0 + kv)];
            As[kv + 0][row] = f.x; As[kv + 1][row] = f.y;
            As[kv + 2][row] = f.z; As[kv + 3][row] = f.w;
        }
        #pragma unroll
        for (int i = 0; i < 2; i++) {
            int idx = tid + i * 256;
            int kr  = idx >> 5;
            int col = (idx & 31) * 4;
            *(float4*)&Bs[kr][col] = *(const float4*)&B[(k0 + kr) * HH + col];
        }
        __syncthreads();
        #pragma unroll
        for (int kk = 0; kk < 16; kk++) {
            float ar[8], br[8];
            #pragma unroll
            for (int i = 0; i < 8; i++) ar[i] = As[kk][tr + i];
            #pragma unroll
            for (int j = 0; j < 8; j++) br[j] = Bs[kk][tc + j];
            #pragma unroll
            for (int i = 0; i < 8; i++)
                #pragma unroll
                for (int j = 0; j < 8; j++) acc[i][j] += ar[i] * br[j];
        }
        __syncthreads();
    }
    #pragma unroll
    for (int i = 0; i < 8; i++)
        #pragma unroll
        for (int j = 0; j < 8; j++) {
            float v = acc[i][j] + bias[tc + j];
            g_h[(bm + tr + i) * HH + (tc + j)] = fmaxf(v, 0.f);
        }
}

// ---------------- 3xBF16 mma.sync rule-mix GEMM ----------------
// g_msg[m, o] += sum_k (w[m, k>>7] * h[m, k&127]) * Wc^T[o, k],  K = 2048
// block tile 128x128, 8 warps (2m x 4n), warp tile 64x32, chunk K=32, double buffered
// per chunk: acc += Ahi*Bhi + Alo*Bhi + Ahi*Blo (bf16 splits, ~2^-18 product error)
__global__ __launch_bounds__(256, 2) void k_mma(int layer) {
    extern __shared__ float sm[];
    const uint32_t smBase = smem_u32(sm);
    uint32_t* SW = (uint32_t*)sm;

    const __nv_bfloat16* __restrict__ BtHi = g_BtHi + (size_t)layer * (HH * KTOT);
    const __nv_bfloat16* __restrict__ BtLo = g_BtLo + (size_t)layer * (HH * KTOT);
    const int tid  = threadIdx.x;
    const int m0   = blockIdx.x * 128;
    const int warp = tid >> 5, lane = tid & 31;
    const int mwarp = warp >> 2;          // 0..1
    const int nwarp = warp & 3;           // 0..3
    const int g   = lane >> 2;            // 0..7
    const int tig = lane & 3;             // 0..3

    // A-fill mapping: 4 iterations x (row, seg); seg = 4 fp32 elements -> 2 packed words
    const int frow = tid >> 3;            // 0..31 (+32 per iter)
    const int fseg = tid & 7;             // 0..7

    // B cp.async mapping: row = tid>>2 (+64), piece = tid&3 (16B pieces)
    const int brow = tid >> 2;
    const int bpc  = tid & 3;

    float acc[4][4][4];
    #pragma unroll
    for (int mi = 0; mi < 4; mi++)
        #pragma unroll
        for (int ni = 0; ni < 4; ni++)
            #pragma unroll
            for (int v = 0; v < 4; v++) acc[mi][ni][v] = 0.f;

    float4 aRegs[4];
    float  wRegs[4];

    auto ldgA = [&](int c) {
        const int cb = (c & 3) * 32;
        const int r  = c >> 2;
        #pragma unroll
        for (int i = 0; i < 4; i++) {
            int row = frow + i * 32;
            aRegs[i] = *(const float4*)&g_h[(size_t)(m0 + row) * HH + cb + fseg * 4];
            wRegs[i] = __ldg(&g_w[(m0 + row) * RR + r]);
        }
    };
    auto stsA = [&](int stage) {
        #pragma unroll
        for (int i = 0; i < 4; i++) {
            int row = frow + i * 32;
            uint32_t addr = smBase + (stage * STAGE_W + row * AST + fseg * 2) * 4;
            float w = wRegs[i];
            float x0 = aRegs[i].x * w, x1 = aRegs[i].y * w;
            float x2 = aRegs[i].z * w, x3 = aRegs[i].w * w;
            __nv_bfloat16 h0 = __float2bfloat16(x0), h1 = __float2bfloat16(x1);
            __nv_bfloat16 h2 = __float2bfloat16(x2), h3 = __float2bfloat16(x3);
            uint32_t hw0, hw1;
            { __nv_bfloat162 t; t.x = h0; t.y = h1; hw0 = *(uint32_t*)&t; }
            { __nv_bfloat162 t; t.x = h2; t.y = h3; hw1 = *(uint32_t*)&t; }
            sts_v2u(addr, hw0, hw1);
            uint32_t lw0 = pack_bf2(x0 - __bfloat162float(h0), x1 - __bfloat162float(h1));
            uint32_t lw1 = pack_bf2(x2 - __bfloat162float(h2), x3 - __bfloat162float(h3));
            sts_v2u(addr + TILE_W * 4, lw0, lw1);
        }
    };
    auto cpB = [&](int c, int stage) {
        const int k0 = c * 32;
        #pragma unroll
        for (int i = 0; i < 2; i++) {
            int n = brow + i * 64;
            size_t gsrc = (size_t)n * KTOT + k0 + bpc * 8;
            uint32_t dst = smBase + (stage * STAGE_W + 2 * TILE_W + n * AST + bpc * 4) * 4;
            cp_async16(dst, &BtHi[gsrc]);
            cp_async16(dst + TILE_W * 4, &BtLo[gsrc]);
        }
        cp_commit();
    };

    auto mmaChunk = [&](int stage) {
        const uint32_t* Ah = SW + stage * STAGE_W;
        const uint32_t* Al = Ah + TILE_W;
        const uint32_t* Bh = Ah + 2 * TILE_W;
        const uint32_t* Bl = Ah + 3 * TILE_W;
        #pragma unroll
        for (int ks = 0; ks < 2; ks++) {
            const int kw = ks * 8 + tig;
            uint32_t bh[4][2], bl[4][2];
            #pragma unroll
            for (int ni = 0; ni < 4; ni++) {
                int n = nwarp * 32 + ni * 8 + g;
                bh[ni][0] = Bh[n * AST + kw];
                bh[ni][1] = Bh[n * AST + kw + 4];
                bl[ni][0] = Bl[n * AST + kw];
                bl[ni][1] = Bl[n * AST + kw + 4];
            }
            #pragma unroll
            for (int mi = 0; mi < 4; mi++) {
                int m = mwarp * 64 + mi * 16;
                uint32_t ah[4], al[4];
                ah[0] = Ah[(m + g)     * AST + kw];
                ah[1] = Ah[(m + g + 8) * AST + kw];
                ah[2] = Ah[(m + g)     * AST + kw + 4];
                ah[3] = Ah[(m + g + 8) * AST + kw + 4];
                al[0] = Al[(m + g)     * AST + kw];
                al[1] = Al[(m + g + 8) * AST + kw];
                al[2] = Al[(m + g)     * AST + kw + 4];
                al[3] = Al[(m + g + 8) * AST + kw + 4];
                #pragma unroll
                for (int ni = 0; ni < 4; ni++) {
                    mma_bf16(acc[mi][ni], ah, bh[ni]);
                    mma_bf16(acc[mi][ni], al, bh[ni]);
                    mma_bf16(acc[mi][ni], ah, bl[ni]);
                }
            }
        }
    };

    // prologue
    ldgA(0);
    stsA(0);
    cpB(0, 0);

    for (int c = 0; c < NCH; ++c) {
        const int s = c & 1;
        cp_wait0();
        __syncthreads();
        if (c + 1 < NCH) {
            ldgA(c + 1);
            cpB(c + 1, s ^ 1);
        }
        mmaChunk(s);
        if (c + 1 < NCH) stsA(s ^ 1);
    }

    // epilogue: g_msg += acc
    #pragma unroll
    for (int mi = 0; mi < 4; mi++) {
        #pragma unroll
        for (int ni = 0; ni < 4; ni++) {
            int grow = m0 + mwarp * 64 + mi * 16 + g;
            int gcol = nwarp * 32 + ni * 8 + 2 * tig;
            float2* p = (float2*)&g_msg[(size_t)grow * HH + gcol];
            float2 v = *p;
            v.x += acc[mi][ni][0]; v.y += acc[mi][ni][1];
            *p = v;
            float2* q = (float2*)&g_msg[(size_t)(grow + 8) * HH + gcol];
            float2 u = *q;
            u.x += acc[mi][ni][2]; u.y += acc[mi][ni][3];
            *q = u;
        }
    }
}

// ---------------- fuzzy rule memberships + bias preload ----------------
__global__ __launch_bounds__(256) void k_rules(
    const float* __restrict__ cen, const float* __restrict__ wid,
    const float* __restrict__ bcl)
{
    __shared__ float sc[16][128];
    __shared__ float siw[16][128];
    __shared__ float sbc[16][128];
    const int t = threadIdx.x;
    for (int i = t; i < RR * HH; i += 256) {
        ((float*)sc)[i] = cen[i];
        float w = wid[i];
        ((float*)siw)[i] = 1.f / (2.f * w * w);
        ((float*)sbc)[i] = bcl[i];
    }
    __syncthreads();

    const int warp = t >> 5, lane = t & 31;
    const int n = blockIdx.x * 8 + warp;

    float4 h4 = *(const float4*)&g_h[n * HH + lane * 4];
    float sr[16];
    #pragma unroll
    for (int r = 0; r < 16; r++) {
        float4 c  = *(const float4*)&sc[r][lane * 4];
        float4 iw = *(const float4*)&siw[r][lane * 4];
        float dx = h4.x - c.x, dy = h4.y - c.y, dz = h4.z - c.z, dw = h4.w - c.w;
        float p = dx * dx * iw.x + dy * dy * iw.y + dz * dz * iw.z + dw * dw * iw.w;
        #pragma unroll
        for (int o = 16; o; o >>= 1) p += __shfl_xor_sync(0xffffffffu, p, o);
        sr[r] = -p * (1.f / 128.f);
    }
    float m = sr[0];
    #pragma unroll
    for (int r = 1; r < 16; r++) m = fmaxf(m, sr[r]);
    float s = 0.f;
    #pragma unroll
    for (int r = 0; r < 16; r++) { sr[r] = expf(sr[r] - m); s += sr[r]; }
    float inv = 1.f / s;

    float4 acc = {0.f, 0.f, 0.f, 0.f};
    #pragma unroll
    for (int r = 0; r < 16; r++) {
        float wr = sr[r] * inv;
        if (lane == r) g_w[n * RR + r] = wr;
        float4 b = *(const float4*)&sbc[r][lane * 4];
        acc.x += wr * b.x; acc.y += wr * b.y; acc.z += wr * b.z; acc.w += wr * b.w;
    }
    *(float4*)&g_msg[n * HH + lane * 4] = acc;   // bias term; MMA accumulates on top
}

// ---------------- edge aggregation (gather-sum via CSR) + relu(mean) ----------------
__global__ __launch_bounds__(256) void k_aggregate() {
    const int warp = threadIdx.x >> 5, lane = threadIdx.x & 31;
    const int n = blockIdx.x * 8 + warp;
    int s0 = g_rowptr[n], s1 = g_rowptr[n + 1];
    float4 acc = {0.f, 0.f, 0.f, 0.f};
    const float4* mp = (const float4*)g_msg;
    for (int j = s0; j < s1; j++) {
        int src = g_col[j];
        float4 v = mp[src * 32 + lane];
        acc.x += v.x; acc.y += v.y; acc.z += v.z; acc.w += v.w;
    }
    int d = s1 - s0;
    float invd = 1.f / (float)(d > 0 ? d : 1);
    float4 a;
    a.x = fmaxf(acc.x * invd, 0.f);
    a.y = fmaxf(acc.y * invd, 0.f);
    a.z = fmaxf(acc.z * invd, 0.f);
    a.w = fmaxf(acc.w * invd, 0.f);
    *(float4*)&g_a[n * HH + lane * 4] = a;
}

// ---------------- batchnorm ----------------
__global__ void k_zero_stats() {
    int t = threadIdx.x;
    if (t < HH) { g_sum[t] = 0.f; g_sumsq[t] = 0.f; }
}

__global__ __launch_bounds__(128) void k_bn_stats() {
    const int t = threadIdx.x;
    float s = 0.f, q = 0.f;
    for (int row = blockIdx.x; row < NN; row += gridDim.x) {
        float v = g_a[row * HH + t];
        s += v; q += v * v;
    }
    atomicAdd(&g_sum[t], s);
    atomicAdd(&g_sumsq[t], q);
}

__global__ __launch_bounds__(128) void k_bn_apply(
    const float* __restrict__ gamma, const float* __restrict__ beta)
{
    const int t = threadIdx.x;
    const float inv_n = 1.f / (float)NN;
    float mu  = g_sum[t] * inv_n;
    float var = g_sumsq[t] * inv_n - mu * mu;
    float sc = gamma[t] * rsqrtf(var + EPS);
    float bb = beta[t];
    for (int row = blockIdx.x; row < NN; row += gridDim.x) {
        int idx = row * HH + t;
        g_h[idx] += (g_a[idx] - mu) * sc + bb;
    }
}

// ---------------- head: out = softmax(h @ W_head + b_head) ----------------
__global__ __launch_bounds__(128) void k_head(
    const float* __restrict__ W, const float* __restrict__ b, float* __restrict__ out)
{
    __shared__ float hs[HH];
    __shared__ float lg[OUTC];
    __shared__ float red[2];
    const int t = threadIdx.x;
    const int n = blockIdx.x;
    hs[t] = g_h[n * HH + t];
    __syncthreads();
    if (t < OUTC) {
        float acc = b[t];
        #pragma unroll 8
        for (int k = 0; k < HH; k++) acc += hs[k] * W[k * OUTC + t];
        lg[t] = acc;
    }
    __syncthreads();
    if (t == 0) {
        float m = lg[0];
        for (int i = 1; i < OUTC; i++) m = fmaxf(m, lg[i]);
        red[0] = m;
    }
    __syncthreads();
    if (t < OUTC) lg[t] = expf(lg[t] - red[0]);
    __syncthreads();
    if (t == 0) {
        float s = 0.f;
        for (int i = 0; i < OUTC; i++) s += lg[i];
        red[1] = 1.f / s;
    }
    __syncthreads();
    if (t < OUTC) out[n * OUTC + t] = lg[t] * red[1];
}

// ---------------- launch ----------------
extern "C" void kernel_launch(void* const* d_in, const int* in_sizes, int n_in,
                              void* d_out, int out_size)
{
    const float* x      = (const float*)d_in[0];
    const int*   ei     = (const int*)d_in[1];
    const float* W_in   = (const float*)d_in[2];
    const float* b_in   = (const float*)d_in[3];
    const float* cen    = (const float*)d_in[4];
    const float* wid    = (const float*)d_in[5];
    const float* Wc     = (const float*)d_in[6];
    const float* bc     = (const float*)d_in[7];
    const float* gamma  = (const float*)d_in[8];
    const float* beta   = (const float*)d_in[9];
    const float* W_head = (const float*)d_in[10];
    const float* b_head = (const float*)d_in[11];
    float* out = (float*)d_out;

    const int E = in_sizes[1] / 2;
    const int* src = ei;
    const int* dst = ei + E;

    const int MMA_SMEM = 2 * STAGE_W * 4;   // 81920 bytes
    cudaFuncSetAttribute(k_mma, cudaFuncAttributeMaxDynamicSharedMemorySize, MMA_SMEM);

    // CSR build
    k_zero_csr<<<(NN + 255) / 256, 256>>>();
    k_count<<<(E + 255) / 256, 256>>>(dst, E);
    k_scan<<<1, 1024>>>(E);
    k_fill<<<(E + 255) / 256, 256>>>(src, dst, E);

    // Wc transpose + hi/lo bf16 split
    k_transB<<<(3 * KTOT * HH) / 256, 256>>>(Wc);

    // input layer: h = relu(x @ W_in + b_in)
    k_gemm_in<<<NN / 128, 256>>>(x, W_in, b_in);

    for (int l = 0; l < 3; l++) {
        const float* cen_l = cen + l * RR * HH;
        const float* wid_l = wid + l * RR * HH;
        const float* bc_l  = bc + l * RR * HH;
        k_rules<<<NN / 8, 256>>>(cen_l, wid_l, bc_l);
        k_mma<<<NN / 128, 256, MMA_SMEM>>>(l);
        k_aggregate<<<NN / 8, 256>>>();
        k_zero_stats<<<1, 128>>>();
        k_bn_stats<<<512, 128>>>();
        k_bn_apply<<<2048, 128>>>(gamma + l * HH, beta + l * HH);
    }

    k_head<<<NN, 128>>>(W_head, b_head, out);
}

// round 6
// speedup vs baseline: 1.7543x; 1.0391x over previous
#include <cuda_runtime.h>
#include <cuda_bf16.h>
#include <cstdint>

// ---------------- problem constants ----------------
constexpr int NN  = 32768;   // nodes
constexpr int HH  = 128;     // hidden
constexpr int RR  = 16;      // rules
constexpr int OUTC = 40;     // output classes
constexpr float EPS = 1e-5f;
constexpr int KTOT = RR * HH;   // 2048
constexpr int KC   = 32;        // K per pipeline chunk
constexpr int NCH  = KTOT / KC; // 64
constexpr int AST  = 20;        // 32-bit words per 32-k row (16 data + 4 pad, conflict-free)
constexpr int TILE_W  = 128 * AST;   // words per tile
constexpr int STAGE_W = 4 * TILE_W;  // Ahi, Alo, Bhi, Blo

// ---------------- device scratch ----------------
__device__ __align__(16) float g_h[NN * HH];          // node features (running)
__device__ __align__(16) float g_msg[NN * HH];        // per-node message
__device__ __align__(16) float g_a[NN * HH];          // post-aggregation activation
__device__ __align__(16) __nv_bfloat16 g_BtHi[3 * HH * KTOT]; // Wc^T hi: [l][o][k]
__device__ __align__(16) __nv_bfloat16 g_BtLo[3 * HH * KTOT]; // Wc^T lo residual
__device__ float g_w[NN * RR];                        // firing strengths
__device__ int   g_deg[NN];
__device__ int   g_cursor[NN];
__device__ int   g_rowptr[NN + 1];
__device__ int   g_col[1 << 20];
__device__ float g_sum[HH];
__device__ float g_sumsq[HH];

// ---------------- helpers ----------------
__device__ __forceinline__ uint32_t smem_u32(const void* p) {
    uint32_t a;
    asm("{ .reg .u64 t; cvta.to.shared.u64 t, %1; cvt.u32.u64 %0, t; }" : "=r"(a) : "l"(p));
    return a;
}
__device__ __forceinline__ void cp_async16(uint32_t dst, const void* src) {
    asm volatile("cp.async.cg.shared.global [%0], [%1], 16;" :: "r"(dst), "l"(src));
}
__device__ __forceinline__ void cp_commit() {
    asm volatile("cp.async.commit_group;");
}
__device__ __forceinline__ void cp_wait0() {
    asm volatile("cp.async.wait_group 0;" ::: "memory");
}
__device__ __forceinline__ void sts_v2u(uint32_t addr, uint32_t a, uint32_t b) {
    asm volatile("st.shared.v2.b32 [%0], {%1, %2};" :: "r"(addr), "r"(a), "r"(b) : "memory");
}
__device__ __forceinline__ uint32_t pack_bf2(float a, float b) {
    __nv_bfloat162 t;
    t.x = __float2bfloat16(a);
    t.y = __float2bfloat16(b);
    return *(uint32_t*)&t;
}
__device__ __forceinline__ void mma_bf16(float* d, const uint32_t* a, const uint32_t* b) {
    asm volatile(
        "mma.sync.aligned.m16n8k16.row.col.f32.bf16.bf16.f32 "
        "{%0, %1, %2, %3}, {%4, %5, %6, %7}, {%8, %9}, {%0, %1, %2, %3};"
        : "+f"(d[0]), "+f"(d[1]), "+f"(d[2]), "+f"(d[3])
        : "r"(a[0]), "r"(a[1]), "r"(a[2]), "r"(a[3]), "r"(b[0]), "r"(b[1]));
}

// ---------------- CSR build ----------------
__global__ void k_zero_csr() {
    int i = blockIdx.x * blockDim.x + threadIdx.x;
    if (i < NN) { g_deg[i] = 0; g_cursor[i] = 0; }
}

__global__ void k_count(const int* __restrict__ dst, int E) {
    int e = blockIdx.x * blockDim.x + threadIdx.x;
    if (e < E) atomicAdd(&g_deg[dst[e]], 1);
}

__global__ void k_scan(int E) {
    __shared__ int sh[1024];
    int t = threadIdx.x;
    int cnt[32];
    int tot = 0;
    #pragma unroll
    for (int i = 0; i < 32; i++) { cnt[i] = g_deg[t * 32 + i]; tot += cnt[i]; }
    sh[t] = tot;
    __syncthreads();
    for (int off = 1; off < 1024; off <<= 1) {
        int v = (t >= off) ? sh[t - off] : 0;
        __syncthreads();
        sh[t] += v;
        __syncthreads();
    }
    int base = sh[t] - tot;
    #pragma unroll
    for (int i = 0; i < 32; i++) { g_rowptr[t * 32 + i] = base; base += cnt[i]; }
    if (t == 1023) g_rowptr[NN] = E;
}

__global__ void k_fill(const int* __restrict__ src, const int* __restrict__ dst, int E) {
    int e = blockIdx.x * blockDim.x + threadIdx.x;
    if (e < E) {
        int d = dst[e];
        int p = atomicAdd(&g_cursor[d], 1);
        g_col[g_rowptr[d] + p] = src[e];
    }
}

// ---------------- Wc transpose + hi/lo bf16 split ----------------
__global__ void k_transB(const float* __restrict__ Wc) {
    int idx = blockIdx.x * blockDim.x + threadIdx.x;  // 3*2048*128 total
    int l = idx >> 18;
    int rem = idx & 262143;
    int k = rem >> 7;
    int o = rem & 127;
    float v = Wc[idx];
    __nv_bfloat16 hi = __float2bfloat16(v);
    __nv_bfloat16 lo = __float2bfloat16(v - __bfloat162float(hi));
    size_t di = (size_t)l * 262144 + (size_t)o * KTOT + k;
    g_BtHi[di] = hi;
    g_BtLo[di] = lo;
}

// ---------------- input SGEMM (fp32): g_h = relu(x @ W_in + b_in), K=128 ----------------
__global__ __launch_bounds__(256, 2) void k_gemm_in(
    const float* __restrict__ A, const float* __restrict__ B,
    const float* __restrict__ bias)
{
    __shared__ float As[16][128];
    __shared__ float Bs[16][128];
    const int tid = threadIdx.x;
    const int bm = blockIdx.x * 128;
    const int tr = (tid / 16) * 8;
    const int tc = (tid % 16) * 8;

    float acc[8][8];
    #pragma unroll
    for (int i = 0; i < 8; i++)
        #pragma unroll
        for (int j = 0; j < 8; j++) acc[i][j] = 0.f;

    for (int k0 = 0; k0 < 128; k0 += 16) {
        #pragma unroll
        for (int i = 0; i < 2; i++) {
            int idx = tid + i * 256;
            int row = idx >> 2;
            int kv  = (idx & 3) * 4;
            float4 f = *(const float4*)&A[(bm + row) * HH + (k0 + kv)];
            As[kv + 0][row] = f.x; As[kv + 1][row] = f.y;
            As[kv + 2][row] = f.z; As[kv + 3][row] = f.w;
        }
        #pragma unroll
        for (int i = 0; i < 2; i++) {
            int idx = tid + i * 256;
            int kr  = idx >> 5;
            int col = (idx & 31) * 4;
            *(float4*)&Bs[kr][col] = *(const float4*)&B[(k0 + kr) * HH + col];
        }
        __syncthreads();
        #pragma unroll
        for (int kk = 0; kk < 16; kk++) {
            float ar[8], br[8];
            #pragma unroll
            for (int i = 0; i < 8; i++) ar[i] = As[kk][tr + i];
            #pragma unroll
            for (int j = 0; j < 8; j++) br[j] = Bs[kk][tc + j];
            #pragma unroll
            for (int i = 0; i < 8; i++)
                #pragma unroll
                for (int j = 0; j < 8; j++) acc[i][j] += ar[i] * br[j];
        }
        __syncthreads();
    }
    #pragma unroll
    for (int i = 0; i < 8; i++)
        #pragma unroll
        for (int j = 0; j < 8; j++) {
            float v = acc[i][j] + bias[tc + j];
            g_h[(bm + tr + i) * HH + (tc + j)] = fmaxf(v, 0.f);
        }
}

// ---------------- 3xBF16 mma.sync rule-mix GEMM ----------------
// g_msg[m, o] += sum_k (w[m, k>>7] * h[m, k&127]) * Wc^T[o, k],  K = 2048
// block tile 128x128, 4 warps (2m x 2n), warp tile 64x64 (Mi=4, Ni=8),
// chunk K=32, double buffered.
// per chunk: acc += Ahi*Bhi + Alo*Bhi + Ahi*Blo (bf16 splits, ~2^-16 product error)
__global__ __launch_bounds__(128, 2) void k_mma(int layer) {
    extern __shared__ float sm[];
    const uint32_t smBase = smem_u32(sm);
    uint32_t* SW = (uint32_t*)sm;

    const __nv_bfloat16* __restrict__ BtHi = g_BtHi + (size_t)layer * (HH * KTOT);
    const __nv_bfloat16* __restrict__ BtLo = g_BtLo + (size_t)layer * (HH * KTOT);
    const int tid  = threadIdx.x;
    const int m0   = blockIdx.x * 128;
    const int warp = tid >> 5, lane = tid & 31;
    const int mwarp = warp >> 1;          // 0..1
    const int nwarp = warp & 1;           // 0..1
    const int g   = lane >> 2;            // 0..7
    const int tig = lane & 3;             // 0..3

    // A-fill mapping: 8 iterations x (row, seg); seg = 4 fp32 -> 2 packed words
    const int frow = tid >> 3;            // 0..15 (+16 per iter)
    const int fseg = tid & 7;             // 0..7

    // B cp.async mapping: row = tid>>2 (+32 per iter), piece = tid&3 (16B pieces)
    const int brow = tid >> 2;            // 0..31
    const int bpc  = tid & 3;

    float acc[4][8][4];
    #pragma unroll
    for (int mi = 0; mi < 4; mi++)
        #pragma unroll
        for (int ni = 0; ni < 8; ni++)
            #pragma unroll
            for (int v = 0; v < 4; v++) acc[mi][ni][v] = 0.f;

    float4 aRegs[8];
    float  wRegs[8];

    auto ldgA = [&](int c) {
        const int cb = (c & 3) * 32;
        const int r  = c >> 2;
        #pragma unroll
        for (int i = 0; i < 8; i++) {
            int row = frow + i * 16;
            aRegs[i] = *(const float4*)&g_h[(size_t)(m0 + row) * HH + cb + fseg * 4];
            wRegs[i] = __ldg(&g_w[(m0 + row) * RR + r]);
        }
    };
    auto stsA = [&](int stage) {
        #pragma unroll
        for (int i = 0; i < 8; i++) {
            int row = frow + i * 16;
            uint32_t addr = smBase + (stage * STAGE_W + row * AST + fseg * 2) * 4;
            float w = wRegs[i];
            float x0 = aRegs[i].x * w, x1 = aRegs[i].y * w;
            float x2 = aRegs[i].z * w, x3 = aRegs[i].w * w;
            __nv_bfloat16 h0 = __float2bfloat16(x0), h1 = __float2bfloat16(x1);
            __nv_bfloat16 h2 = __float2bfloat16(x2), h3 = __float2bfloat16(x3);
            uint32_t hw0, hw1;
            { __nv_bfloat162 t; t.x = h0; t.y = h1; hw0 = *(uint32_t*)&t; }
            { __nv_bfloat162 t; t.x = h2; t.y = h3; hw1 = *(uint32_t*)&t; }
            sts_v2u(addr, hw0, hw1);
            uint32_t lw0 = pack_bf2(x0 - __bfloat162float(h0), x1 - __bfloat162float(h1));
            uint32_t lw1 = pack_bf2(x2 - __bfloat162float(h2), x3 - __bfloat162float(h3));
            sts_v2u(addr + TILE_W * 4, lw0, lw1);
        }
    };
    auto cpB = [&](int c, int stage) {
        const int k0 = c * 32;
        #pragma unroll
        for (int i = 0; i < 4; i++) {
            int n = brow + i * 32;
            size_t gsrc = (size_t)n * KTOT + k0 + bpc * 8;
            uint32_t dst = smBase + (stage * STAGE_W + 2 * TILE_W + n * AST + bpc * 4) * 4;
            cp_async16(dst, &BtHi[gsrc]);
            cp_async16(dst + TILE_W * 4, &BtLo[gsrc]);
        }
        cp_commit();
    };

    auto mmaChunk = [&](int stage) {
        const uint32_t* Ah = SW + stage * STAGE_W;
        const uint32_t* Al = Ah + TILE_W;
        const uint32_t* Bh = Ah + 2 * TILE_W;
        const uint32_t* Bl = Ah + 3 * TILE_W;
        #pragma unroll
        for (int ks = 0; ks < 2; ks++) {
            const int kw = ks * 8 + tig;
            uint32_t bh[8][2], bl[8][2];
            #pragma unroll
            for (int ni = 0; ni < 8; ni++) {
                int n = nwarp * 64 + ni * 8 + g;
                bh[ni][0] = Bh[n * AST + kw];
                bh[ni][1] = Bh[n * AST + kw + 4];
                bl[ni][0] = Bl[n * AST + kw];
                bl[ni][1] = Bl[n * AST + kw + 4];
            }
            #pragma unroll
            for (int mi = 0; mi < 4; mi++) {
                int m = mwarp * 64 + mi * 16;
                uint32_t ah[4], al[4];
                ah[0] = Ah[(m + g)     * AST + kw];
                ah[1] = Ah[(m + g + 8) * AST + kw];
                ah[2] = Ah[(m + g)     * AST + kw + 4];
                ah[3] = Ah[(m + g + 8) * AST + kw + 4];
                al[0] = Al[(m + g)     * AST + kw];
                al[1] = Al[(m + g + 8) * AST + kw];
                al[2] = Al[(m + g)     * AST + kw + 4];
                al[3] = Al[(m + g + 8) * AST + kw + 4];
                #pragma unroll
                for (int ni = 0; ni < 8; ni++) {
                    mma_bf16(acc[mi][ni], ah, bh[ni]);
                    mma_bf16(acc[mi][ni], al, bh[ni]);
                    mma_bf16(acc[mi][ni], ah, bl[ni]);
                }
            }
        }
    };

    // prologue
    ldgA(0);
    stsA(0);
    cpB(0, 0);

    for (int c = 0; c < NCH; ++c) {
        const int s = c & 1;
        cp_wait0();
        __syncthreads();
        if (c + 1 < NCH) {
            ldgA(c + 1);
            cpB(c + 1, s ^ 1);
        }
        mmaChunk(s);
        if (c + 1 < NCH) stsA(s ^ 1);
    }

    // epilogue: g_msg += acc
    #pragma unroll
    for (int mi = 0; mi < 4; mi++) {
        #pragma unroll
        for (int ni = 0; ni < 8; ni++) {
            int grow = m0 + mwarp * 64 + mi * 16 + g;
            int gcol = nwarp * 64 + ni * 8 + 2 * tig;
            float2* p = (float2*)&g_msg[(size_t)grow * HH + gcol];
            float2 v = *p;
            v.x += acc[mi][ni][0]; v.y += acc[mi][ni][1];
            *p = v;
            float2* q = (float2*)&g_msg[(size_t)(grow + 8) * HH + gcol];
            float2 u = *q;
            u.x += acc[mi][ni][2]; u.y += acc[mi][ni][3];
            *q = u;
        }
    }
}

// ---------------- fuzzy rule memberships + bias preload ----------------
__global__ __launch_bounds__(256) void k_rules(
    const float* __restrict__ cen, const float* __restrict__ wid,
    const float* __restrict__ bcl)
{
    __shared__ float sc[16][128];
    __shared__ float siw[16][128];
    __shared__ float sbc[16][128];
    const int t = threadIdx.x;
    for (int i = t; i < RR * HH; i += 256) {
        ((float*)sc)[i] = cen[i];
        float w = wid[i];
        ((float*)siw)[i] = 1.f / (2.f * w * w);
        ((float*)sbc)[i] = bcl[i];
    }
    __syncthreads();

    const int warp = t >> 5, lane = t & 31;
    const int n = blockIdx.x * 8 + warp;

    float4 h4 = *(const float4*)&g_h[n * HH + lane * 4];
    float sr[16];
    #pragma unroll
    for (int r = 0; r < 16; r++) {
        float4 c  = *(const float4*)&sc[r][lane * 4];
        float4 iw = *(const float4*)&siw[r][lane * 4];
        float dx = h4.x - c.x, dy = h4.y - c.y, dz = h4.z - c.z, dw = h4.w - c.w;
        float p = dx * dx * iw.x + dy * dy * iw.y + dz * dz * iw.z + dw * dw * iw.w;
        #pragma unroll
        for (int o = 16; o; o >>= 1) p += __shfl_xor_sync(0xffffffffu, p, o);
        sr[r] = -p * (1.f / 128.f);
    }
    float m = sr[0];
    #pragma unroll
    for (int r = 1; r < 16; r++) m = fmaxf(m, sr[r]);
    float s = 0.f;
    #pragma unroll
    for (int r = 0; r < 16; r++) { sr[r] = expf(sr[r] - m); s += sr[r]; }
    float inv = 1.f / s;

    float4 acc = {0.f, 0.f, 0.f, 0.f};
    #pragma unroll
    for (int r = 0; r < 16; r++) {
        float wr = sr[r] * inv;
        if (lane == r) g_w[n * RR + r] = wr;
        float4 b = *(const float4*)&sbc[r][lane * 4];
        acc.x += wr * b.x; acc.y += wr * b.y; acc.z += wr * b.z; acc.w += wr * b.w;
    }
    *(float4*)&g_msg[n * HH + lane * 4] = acc;   // bias term; MMA accumulates on top
}

// ---------------- edge aggregation (gather-sum via CSR) + relu(mean) ----------------
__global__ __launch_bounds__(256) void k_aggregate() {
    const int warp = threadIdx.x >> 5, lane = threadIdx.x & 31;
    const int n = blockIdx.x * 8 + warp;
    int s0 = g_rowptr[n], s1 = g_rowptr[n + 1];
    float4 acc = {0.f, 0.f, 0.f, 0.f};
    const float4* mp = (const float4*)g_msg;
    for (int j = s0; j < s1; j++) {
        int src = g_col[j];
        float4 v = mp[src * 32 + lane];
        acc.x += v.x; acc.y += v.y; acc.z += v.z; acc.w += v.w;
    }
    int d = s1 - s0;
    float invd = 1.f / (float)(d > 0 ? d : 1);
    float4 a;
    a.x = fmaxf(acc.x * invd, 0.f);
    a.y = fmaxf(acc.y * invd, 0.f);
    a.z = fmaxf(acc.z * invd, 0.f);
    a.w = fmaxf(acc.w * invd, 0.f);
    *(float4*)&g_a[n * HH + lane * 4] = a;
}

// ---------------- batchnorm ----------------
__global__ void k_zero_stats() {
    int t = threadIdx.x;
    if (t < HH) { g_sum[t] = 0.f; g_sumsq[t] = 0.f; }
}

__global__ __launch_bounds__(128) void k_bn_stats() {
    const int t = threadIdx.x;
    float s = 0.f, q = 0.f;
    for (int row = blockIdx.x; row < NN; row += gridDim.x) {
        float v = g_a[row * HH + t];
        s += v; q += v * v;
    }
    atomicAdd(&g_sum[t], s);
    atomicAdd(&g_sumsq[t], q);
}

__global__ __launch_bounds__(128) void k_bn_apply(
    const float* __restrict__ gamma, const float* __restrict__ beta)
{
    const int t = threadIdx.x;
    const float inv_n = 1.f / (float)NN;
    float mu  = g_sum[t] * inv_n;
    float var = g_sumsq[t] * inv_n - mu * mu;
    float sc = gamma[t] * rsqrtf(var + EPS);
    float bb = beta[t];
    for (int row = blockIdx.x; row < NN; row += gridDim.x) {
        int idx = row * HH + t;
        g_h[idx] += (g_a[idx] - mu) * sc + bb;
    }
}

// ---------------- head: out = softmax(h @ W_head + b_head) ----------------
__global__ __launch_bounds__(128) void k_head(
    const float* __restrict__ W, const float* __restrict__ b, float* __restrict__ out)
{
    __shared__ float hs[HH];
    __shared__ float lg[OUTC];
    __shared__ float red[2];
    const int t = threadIdx.x;
    const int n = blockIdx.x;
    hs[t] = g_h[n * HH + t];
    __syncthreads();
    if (t < OUTC) {
        float acc = b[t];
        #pragma unroll 8
        for (int k = 0; k < HH; k++) acc += hs[k] * W[k * OUTC + t];
        lg[t] = acc;
    }
    __syncthreads();
    if (t == 0) {
        float m = lg[0];
        for (int i = 1; i < OUTC; i++) m = fmaxf(m, lg[i]);
        red[0] = m;
    }
    __syncthreads();
    if (t < OUTC) lg[t] = expf(lg[t] - red[0]);
    __syncthreads();
    if (t == 0) {
        float s = 0.f;
        for (int i = 0; i < OUTC; i++) s += lg[i];
        red[1] = 1.f / s;
    }
    __syncthreads();
    if (t < OUTC) out[n * OUTC + t] = lg[t] * red[1];
}

// ---------------- launch ----------------
extern "C" void kernel_launch(void* const* d_in, const int* in_sizes, int n_in,
                              void* d_out, int out_size)
{
    const float* x      = (const float*)d_in[0];
    const int*   ei     = (const int*)d_in[1];
    const float* W_in   = (const float*)d_in[2];
    const float* b_in   = (const float*)d_in[3];
    const float* cen    = (const float*)d_in[4];
    const float* wid    = (const float*)d_in[5];
    const float* Wc     = (const float*)d_in[6];
    const float* bc     = (const float*)d_in[7];
    const float* gamma  = (const float*)d_in[8];
    const float* beta   = (const float*)d_in[9];
    const float* W_head = (const float*)d_in[10];
    const float* b_head = (const float*)d_in[11];
    float* out = (float*)d_out;

    const int E = in_sizes[1] / 2;
    const int* src = ei;
    const int* dst = ei + E;

    const int MMA_SMEM = 2 * STAGE_W * 4;   // 81920 bytes
    cudaFuncSetAttribute(k_mma, cudaFuncAttributeMaxDynamicSharedMemorySize, MMA_SMEM);

    // CSR build
    k_zero_csr<<<(NN + 255) / 256, 256>>>();
    k_count<<<(E + 255) / 256, 256>>>(dst, E);
    k_scan<<<1, 1024>>>(E);
    k_fill<<<(E + 255) / 256, 256>>>(src, dst, E);

    // Wc transpose + hi/lo bf16 split
    k_transB<<<(3 * KTOT * HH) / 256, 256>>>(Wc);

    // input layer: h = relu(x @ W_in + b_in)
    k_gemm_in<<<NN / 128, 256>>>(x, W_in, b_in);

    for (int l = 0; l < 3; l++) {
        const float* cen_l = cen + l * RR * HH;
        const float* wid_l = wid + l * RR * HH;
        const float* bc_l  = bc + l * RR * HH;
        k_rules<<<NN / 8, 256>>>(cen_l, wid_l, bc_l);
        k_mma<<<NN / 128, 128, MMA_SMEM>>>(l);
        k_aggregate<<<NN / 8, 256>>>();
        k_zero_stats<<<1, 128>>>();
        k_bn_stats<<<512, 128>>>();
        k_bn_apply<<<2048, 128>>>(gamma + l * HH, beta + l * HH);
    }

    k_head<<<NN, 128>>>(W_head, b_head, out);
}

// round 7
// speedup vs baseline: 1.7677x; 1.0076x over previous
#include <cuda_runtime.h>
#include <cuda_bf16.h>
#include <cstdint>

// ---------------- problem constants ----------------
constexpr int NN  = 32768;   // nodes
constexpr int HH  = 128;     // hidden
constexpr int RR  = 16;      // rules
constexpr int OUTC = 40;     // output classes
constexpr float EPS = 1e-5f;
constexpr int KTOT = RR * HH;   // 2048

// k_layer smem word offsets
constexpr int OFF_BC = 0;                 // bc: 16*128 = 2048 w
constexpr int OFF_W  = 2048;              // w:  128*17 = 2176 w
constexpr int OFF_A  = 4224;              // A hi/lo: 2 * 128*68 = 17408 w (cen/siw overlay pre-split)
constexpr int AW     = 68;                // A row stride (64 data + 4 pad)
constexpr int A_TW   = 128 * AW;          // 8704 w per A tile
constexpr int OFF_B  = OFF_A + 2 * A_TW;  // 21632; B: 2 stages * 2 * 128*36 = 18432 w (hraw overlay)
constexpr int BW     = 36;                // B row stride (32 data + 4 pad)
constexpr int B_TW   = 128 * BW;          // 4608 w per B tile
constexpr int B_SW   = 2 * B_TW;          // 9216 w per stage (hi+lo)
constexpr int SMEM_WORDS = OFF_B + 2 * B_SW;     // 40064
constexpr int SMEM_BYTES = SMEM_WORDS * 4;       // 160256

// ---------------- device scratch ----------------
__device__ __align__(16) float g_h[NN * HH];          // node features (running)
__device__ __align__(16) float g_msg[NN * HH];        // per-node message
__device__ __align__(16) float g_a[NN * HH];          // post-aggregation activation
__device__ __align__(16) __nv_bfloat16 g_BtHi[3 * HH * KTOT]; // Wc^T hi: [l][o][k]
__device__ __align__(16) __nv_bfloat16 g_BtLo[3 * HH * KTOT]; // Wc^T lo residual
__device__ int   g_deg[NN];
__device__ int   g_cursor[NN];
__device__ int   g_rowptr[NN + 1];
__device__ int   g_col[1 << 20];
__device__ float g_sum[HH];
__device__ float g_sumsq[HH];

// ---------------- helpers ----------------
__device__ __forceinline__ uint32_t smem_u32(const void* p) {
    uint32_t a;
    asm("{ .reg .u64 t; cvta.to.shared.u64 t, %1; cvt.u32.u64 %0, t; }" : "=r"(a) : "l"(p));
    return a;
}
__device__ __forceinline__ void cp_async16(uint32_t dst, const void* src) {
    asm volatile("cp.async.cg.shared.global [%0], [%1], 16;" :: "r"(dst), "l"(src));
}
__device__ __forceinline__ void cp_commit() {
    asm volatile("cp.async.commit_group;");
}
__device__ __forceinline__ void cp_wait0() {
    asm volatile("cp.async.wait_group 0;" ::: "memory");
}
__device__ __forceinline__ void sts_v2u(uint32_t addr, uint32_t a, uint32_t b) {
    asm volatile("st.shared.v2.b32 [%0], {%1, %2};" :: "r"(addr), "r"(a), "r"(b) : "memory");
}
__device__ __forceinline__ uint32_t pack_bf2(float a, float b) {
    __nv_bfloat162 t;
    t.x = __float2bfloat16(a);
    t.y = __float2bfloat16(b);
    return *(uint32_t*)&t;
}
__device__ __forceinline__ void mma_bf16(float* d, const uint32_t* a, const uint32_t* b) {
    asm volatile(
        "mma.sync.aligned.m16n8k16.row.col.f32.bf16.bf16.f32 "
        "{%0, %1, %2, %3}, {%4, %5, %6, %7}, {%8, %9}, {%0, %1, %2, %3};"
        : "+f"(d[0]), "+f"(d[1]), "+f"(d[2]), "+f"(d[3])
        : "r"(a[0]), "r"(a[1]), "r"(a[2]), "r"(a[3]), "r"(b[0]), "r"(b[1]));
}

// ---------------- CSR build ----------------
__global__ void k_zero_csr() {
    int i = blockIdx.x * blockDim.x + threadIdx.x;
    if (i < NN) { g_deg[i] = 0; g_cursor[i] = 0; }
}

__global__ void k_count(const int* __restrict__ dst, int E) {
    int e = blockIdx.x * blockDim.x + threadIdx.x;
    if (e < E) atomicAdd(&g_deg[dst[e]], 1);
}

__global__ void k_scan(int E) {
    __shared__ int sh[1024];
    int t = threadIdx.x;
    int cnt[32];
    int tot = 0;
    #pragma unroll
    for (int i = 0; i < 32; i++) { cnt[i] = g_deg[t * 32 + i]; tot += cnt[i]; }
    sh[t] = tot;
    __syncthreads();
    for (int off = 1; off < 1024; off <<= 1) {
        int v = (t >= off) ? sh[t - off] : 0;
        __syncthreads();
        sh[t] += v;
        __syncthreads();
    }
    int base = sh[t] - tot;
    #pragma unroll
    for (int i = 0; i < 32; i++) { g_rowptr[t * 32 + i] = base; base += cnt[i]; }
    if (t == 1023) g_rowptr[NN] = E;
}

__global__ void k_fill(const int* __restrict__ src, const int* __restrict__ dst, int E) {
    int e = blockIdx.x * blockDim.x + threadIdx.x;
    if (e < E) {
        int d = dst[e];
        int p = atomicAdd(&g_cursor[d], 1);
        g_col[g_rowptr[d] + p] = src[e];
    }
}

// ---------------- Wc transpose + hi/lo bf16 split ----------------
__global__ void k_transB(const float* __restrict__ Wc) {
    int idx = blockIdx.x * blockDim.x + threadIdx.x;  // 3*2048*128 total
    int l = idx >> 18;
    int rem = idx & 262143;
    int k = rem >> 7;
    int o = rem & 127;
    float v = Wc[idx];
    __nv_bfloat16 hi = __float2bfloat16(v);
    __nv_bfloat16 lo = __float2bfloat16(v - __bfloat162float(hi));
    size_t di = (size_t)l * 262144 + (size_t)o * KTOT + k;
    g_BtHi[di] = hi;
    g_BtLo[di] = lo;
}

// ---------------- input SGEMM (fp32): g_h = relu(x @ W_in + b_in), K=128 ----------------
__global__ __launch_bounds__(256, 2) void k_gemm_in(
    const float* __restrict__ A, const float* __restrict__ B,
    const float* __restrict__ bias)
{
    __shared__ float As[16][128];
    __shared__ float Bs[16][128];
    const int tid = threadIdx.x;
    const int bm = blockIdx.x * 128;
    const int tr = (tid / 16) * 8;
    const int tc = (tid % 16) * 8;

    float acc[8][8];
    #pragma unroll
    for (int i = 0; i < 8; i++)
        #pragma unroll
        for (int j = 0; j < 8; j++) acc[i][j] = 0.f;

    for (int k0 = 0; k0 < 128; k0 += 16) {
        #pragma unroll
        for (int i = 0; i < 2; i++) {
            int idx = tid + i * 256;
            int row = idx >> 2;
            int kv  = (idx & 3) * 4;
            float4 f = *(const float4*)&A[(bm + row) * HH + (k0 + kv)];
            As[kv + 0][row] = f.x; As[kv + 1][row] = f.y;
            As[kv + 2][row] = f.z; As[kv + 3][row] = f.w;
        }
        #pragma unroll
        for (int i = 0; i < 2; i++) {
            int idx = tid + i * 256;
            int kr  = idx >> 5;
            int col = (idx & 31) * 4;
            *(float4*)&Bs[kr][col] = *(const float4*)&B[(k0 + kr) * HH + col];
        }
        __syncthreads();
        #pragma unroll
        for (int kk = 0; kk < 16; kk++) {
            float ar[8], br[8];
            #pragma unroll
            for (int i = 0; i < 8; i++) ar[i] = As[kk][tr + i];
            #pragma unroll
            for (int j = 0; j < 8; j++) br[j] = Bs[kk][tc + j];
            #pragma unroll
            for (int i = 0; i < 8; i++)
                #pragma unroll
                for (int j = 0; j < 8; j++) acc[i][j] += ar[i] * br[j];
        }
        __syncthreads();
    }
    #pragma unroll
    for (int i = 0; i < 8; i++)
        #pragma unroll
        for (int j = 0; j < 8; j++) {
            float v = acc[i][j] + bias[tc + j];
            g_h[(bm + tr + i) * HH + (tc + j)] = fmaxf(v, 0.f);
        }
}

// ---------------- fused layer kernel: rules + 3xBF16 rule-major GEMM ----------------
// msg[m,o] = sum_r w[m,r] * ( (h @ Wc_r)[m,o] + bc[r,o] )
// A (=h) split to bf16 hi/lo ONCE into smem; rules softmax computed in prologue;
// rule-major mainloop: 32 chunks (K=64), B streamed via cp.async double buffer;
// per-rule fp32 flush accT += w*(accR + bc).
__global__ __launch_bounds__(256, 1) void k_layer(
    const float* __restrict__ cen, const float* __restrict__ wid,
    const float* __restrict__ bcl, int layer)
{
    extern __shared__ float sm[];
    const uint32_t smBase = smem_u32(sm);
    uint32_t* SW = (uint32_t*)sm;

    const __nv_bfloat16* __restrict__ BtHi = g_BtHi + (size_t)layer * (HH * KTOT);
    const __nv_bfloat16* __restrict__ BtLo = g_BtLo + (size_t)layer * (HH * KTOT);
    const int tid  = threadIdx.x;
    const int m0   = blockIdx.x * 128;
    const int warp = tid >> 5, lane = tid & 31;
    const int mwarp = warp >> 2;          // 0..1
    const int nwarp = warp & 3;           // 0..3
    const int g   = lane >> 2;            // 0..7
    const int tig = lane & 3;             // 0..3

    // ---- load bc, cen, siw (cen/siw overlay the A region pre-split) ----
    for (int i = tid; i < RR * HH; i += 256) {
        sm[OFF_BC + i] = bcl[i];
        sm[OFF_A + i] = cen[i];
        float w = wid[i];
        sm[OFF_A + 2048 + i] = 1.f / (2.f * w * w);
    }
    // ---- load h tile fp32 into B region (hraw overlay) ----
    #pragma unroll
    for (int i = 0; i < 16; i++) {
        int t = tid + i * 256;
        int row = t >> 5, q = t & 31;
        *(float4*)&sm[OFF_B + row * 128 + q * 4] =
            *(const float4*)&g_h[(size_t)(m0 + row) * HH + q * 4];
    }
    __syncthreads();

    // ---- rules: each warp handles 16 nodes ----
    {
        const float* hraw = sm + OFF_B;
        const float* scen = sm + OFF_A;
        const float* ssiw = sm + OFF_A + 2048;
        for (int i = 0; i < 16; i++) {
            int node = warp * 16 + i;
            float4 h4 = *(const float4*)&hraw[node * 128 + lane * 4];
            float sr[16];
            #pragma unroll
            for (int r = 0; r < 16; r++) {
                float4 c  = *(const float4*)&scen[r * 128 + lane * 4];
                float4 iw = *(const float4*)&ssiw[r * 128 + lane * 4];
                float dx = h4.x - c.x, dy = h4.y - c.y, dz = h4.z - c.z, dw = h4.w - c.w;
                float p = dx * dx * iw.x + dy * dy * iw.y + dz * dz * iw.z + dw * dw * iw.w;
                #pragma unroll
                for (int o = 16; o; o >>= 1) p += __shfl_xor_sync(0xffffffffu, p, o);
                sr[r] = -p * (1.f / 128.f);
            }
            float m = sr[0];
            #pragma unroll
            for (int r = 1; r < 16; r++) m = fmaxf(m, sr[r]);
            float s = 0.f;
            #pragma unroll
            for (int r = 0; r < 16; r++) { sr[r] = expf(sr[r] - m); s += sr[r]; }
            float inv = 1.f / s;
            #pragma unroll
            for (int r = 0; r < 16; r++) {
                if (lane == r) sm[OFF_W + node * 17 + r] = sr[r] * inv;
            }
        }
    }
    __syncthreads();

    // ---- split h -> A hi/lo bf16 tiles (overwrites cen/siw region) ----
    #pragma unroll
    for (int i = 0; i < 16; i++) {
        int t = tid + i * 256;          // 0..4095 float4 units
        int row = t >> 5, seg = t & 31;
        float4 v = *(const float4*)&sm[OFF_B + row * 128 + seg * 4];
        __nv_bfloat16 h0 = __float2bfloat16(v.x), h1 = __float2bfloat16(v.y);
        __nv_bfloat16 h2 = __float2bfloat16(v.z), h3 = __float2bfloat16(v.w);
        uint32_t hw0, hw1;
        { __nv_bfloat162 q; q.x = h0; q.y = h1; hw0 = *(uint32_t*)&q; }
        { __nv_bfloat162 q; q.x = h2; q.y = h3; hw1 = *(uint32_t*)&q; }
        uint32_t dst = smBase + (OFF_A + row * AW + seg * 2) * 4;
        sts_v2u(dst, hw0, hw1);
        uint32_t lw0 = pack_bf2(v.x - __bfloat162float(h0), v.y - __bfloat162float(h1));
        uint32_t lw1 = pack_bf2(v.z - __bfloat162float(h2), v.w - __bfloat162float(h3));
        sts_v2u(dst + A_TW * 4, lw0, lw1);
    }
    __syncthreads();

    // ---- accumulators ----
    float accT[4][4][4], accR[4][4][4];
    #pragma unroll
    for (int mi = 0; mi < 4; mi++)
        #pragma unroll
        for (int ni = 0; ni < 4; ni++)
            #pragma unroll
            for (int v = 0; v < 4; v++) { accT[mi][ni][v] = 0.f; accR[mi][ni][v] = 0.f; }

    // B cp.async: chunk c covers rule r=c>>1, half hf=c&1 -> k0 = r*128 + hf*64
    auto cpB = [&](int c, int stage) {
        const int k0 = (c >> 1) * 128 + (c & 1) * 64;
        #pragma unroll
        for (int i = 0; i < 4; i++) {
            int t = tid + i * 256;      // 0..1023
            int row = t >> 3, pc = t & 7;
            size_t gsrc = (size_t)row * KTOT + k0 + pc * 8;
            uint32_t dst = smBase + (OFF_B + stage * B_SW + row * BW + pc * 4) * 4;
            cp_async16(dst, &BtHi[gsrc]);
            cp_async16(dst + B_TW * 4, &BtLo[gsrc]);
        }
        cp_commit();
    };

    cpB(0, 0);

    for (int c = 0; c < 32; ++c) {
        const int s = c & 1;
        cp_wait0();
        __syncthreads();
        if (c + 1 < 32) cpB(c + 1, s ^ 1);

        const uint32_t* Ah = SW + OFF_A;
        const uint32_t* Al = Ah + A_TW;
        const uint32_t* Bh = SW + OFF_B + s * B_SW;
        const uint32_t* Bl = Bh + B_TW;
        const int abase = (c & 1) * 32;

        #pragma unroll
        for (int ks = 0; ks < 4; ks++) {
            const int kwB = ks * 8 + tig;
            const int kwA = abase + kwB;
            uint32_t bh[4][2], bl[4][2];
            #pragma unroll
            for (int ni = 0; ni < 4; ni++) {
                int n = nwarp * 32 + ni * 8 + g;
                bh[ni][0] = Bh[n * BW + kwB];
                bh[ni][1] = Bh[n * BW + kwB + 4];
                bl[ni][0] = Bl[n * BW + kwB];
                bl[ni][1] = Bl[n * BW + kwB + 4];
            }
            #pragma unroll
            for (int mi = 0; mi < 4; mi++) {
                int m = mwarp * 64 + mi * 16;
                uint32_t ah[4], al[4];
                ah[0] = Ah[(m + g)     * AW + kwA];
                ah[1] = Ah[(m + g + 8) * AW + kwA];
                ah[2] = Ah[(m + g)     * AW + kwA + 4];
                ah[3] = Ah[(m + g + 8) * AW + kwA + 4];
                al[0] = Al[(m + g)     * AW + kwA];
                al[1] = Al[(m + g + 8) * AW + kwA];
                al[2] = Al[(m + g)     * AW + kwA + 4];
                al[3] = Al[(m + g + 8) * AW + kwA + 4];
                #pragma unroll
                for (int ni = 0; ni < 4; ni++) {
                    mma_bf16(accR[mi][ni], ah, bh[ni]);
                    mma_bf16(accR[mi][ni], al, bh[ni]);
                    mma_bf16(accR[mi][ni], ah, bl[ni]);
                }
            }
        }

        if (c & 1) {
            // end of rule r: accT += w * (accR + bc), clear accR
            const int r = c >> 1;
            #pragma unroll
            for (int mi = 0; mi < 4; mi++) {
                int mrow = mwarp * 64 + mi * 16 + g;
                float w0 = sm[OFF_W + mrow * 17 + r];
                float w1 = sm[OFF_W + (mrow + 8) * 17 + r];
                #pragma unroll
                for (int ni = 0; ni < 4; ni++) {
                    int col = nwarp * 32 + ni * 8 + 2 * tig;
                    float bc0 = sm[OFF_BC + r * 128 + col];
                    float bc1 = sm[OFF_BC + r * 128 + col + 1];
                    accT[mi][ni][0] += w0 * (accR[mi][ni][0] + bc0);
                    accT[mi][ni][1] += w0 * (accR[mi][ni][1] + bc1);
                    accT[mi][ni][2] += w1 * (accR[mi][ni][2] + bc0);
                    accT[mi][ni][3] += w1 * (accR[mi][ni][3] + bc1);
                    accR[mi][ni][0] = 0.f; accR[mi][ni][1] = 0.f;
                    accR[mi][ni][2] = 0.f; accR[mi][ni][3] = 0.f;
                }
            }
        }
    }

    // ---- epilogue: pure store of msg ----
    #pragma unroll
    for (int mi = 0; mi < 4; mi++) {
        #pragma unroll
        for (int ni = 0; ni < 4; ni++) {
            int grow = m0 + mwarp * 64 + mi * 16 + g;
            int gcol = nwarp * 32 + ni * 8 + 2 * tig;
            float2 v; v.x = accT[mi][ni][0]; v.y = accT[mi][ni][1];
            *(float2*)&g_msg[(size_t)grow * HH + gcol] = v;
            float2 u; u.x = accT[mi][ni][2]; u.y = accT[mi][ni][3];
            *(float2*)&g_msg[(size_t)(grow + 8) * HH + gcol] = u;
        }
    }
}

// ---------------- edge aggregation (gather-sum via CSR) + relu(mean) ----------------
__global__ __launch_bounds__(256) void k_aggregate() {
    const int warp = threadIdx.x >> 5, lane = threadIdx.x & 31;
    const int n = blockIdx.x * 8 + warp;
    int s0 = g_rowptr[n], s1 = g_rowptr[n + 1];
    float4 acc = {0.f, 0.f, 0.f, 0.f};
    const float4* mp = (const float4*)g_msg;
    for (int j = s0; j < s1; j++) {
        int src = g_col[j];
        float4 v = mp[src * 32 + lane];
        acc.x += v.x; acc.y += v.y; acc.z += v.z; acc.w += v.w;
    }
    int d = s1 - s0;
    float invd = 1.f / (float)(d > 0 ? d : 1);
    float4 a;
    a.x = fmaxf(acc.x * invd, 0.f);
    a.y = fmaxf(acc.y * invd, 0.f);
    a.z = fmaxf(acc.z * invd, 0.f);
    a.w = fmaxf(acc.w * invd, 0.f);
    *(float4*)&g_a[n * HH + lane * 4] = a;
}

// ---------------- batchnorm ----------------
__global__ void k_zero_stats() {
    int t = threadIdx.x;
    if (t < HH) { g_sum[t] = 0.f; g_sumsq[t] = 0.f; }
}

__global__ __launch_bounds__(128) void k_bn_stats() {
    const int t = threadIdx.x;
    float s = 0.f, q = 0.f;
    for (int row = blockIdx.x; row < NN; row += gridDim.x) {
        float v = g_a[row * HH + t];
        s += v; q += v * v;
    }
    atomicAdd(&g_sum[t], s);
    atomicAdd(&g_sumsq[t], q);
}

__global__ __launch_bounds__(128) void k_bn_apply(
    const float* __restrict__ gamma, const float* __restrict__ beta)
{
    const int t = threadIdx.x;
    const float inv_n = 1.f / (float)NN;
    float mu  = g_sum[t] * inv_n;
    float var = g_sumsq[t] * inv_n - mu * mu;
    float sc = gamma[t] * rsqrtf(var + EPS);
    float bb = beta[t];
    for (int row = blockIdx.x; row < NN; row += gridDim.x) {
        int idx = row * HH + t;
        g_h[idx] += (g_a[idx] - mu) * sc + bb;
    }
}

// ---------------- head: out = softmax(h @ W_head + b_head) ----------------
__global__ __launch_bounds__(128) void k_head(
    const float* __restrict__ W, const float* __restrict__ b, float* __restrict__ out)
{
    __shared__ float hs[HH];
    __shared__ float lg[OUTC];
    __shared__ float red[2];
    const int t = threadIdx.x;
    const int n = blockIdx.x;
    hs[t] = g_h[n * HH + t];
    __syncthreads();
    if (t < OUTC) {
        float acc = b[t];
        #pragma unroll 8
        for (int k = 0; k < HH; k++) acc += hs[k] * W[k * OUTC + t];
        lg[t] = acc;
    }
    __syncthreads();
    if (t == 0) {
        float m = lg[0];
        for (int i = 1; i < OUTC; i++) m = fmaxf(m, lg[i]);
        red[0] = m;
    }
    __syncthreads();
    if (t < OUTC) lg[t] = expf(lg[t] - red[0]);
    __syncthreads();
    if (t == 0) {
        float s = 0.f;
        for (int i = 0; i < OUTC; i++) s += lg[i];
        red[1] = 1.f / s;
    }
    __syncthreads();
    if (t < OUTC) out[n * OUTC + t] = lg[t] * red[1];
}

// ---------------- launch ----------------
extern "C" void kernel_launch(void* const* d_in, const int* in_sizes, int n_in,
                              void* d_out, int out_size)
{
    const float* x      = (const float*)d_in[0];
    const int*   ei     = (const int*)d_in[1];
    const float* W_in   = (const float*)d_in[2];
    const float* b_in   = (const float*)d_in[3];
    const float* cen    = (const float*)d_in[4];
    const float* wid    = (const float*)d_in[5];
    const float* Wc     = (const float*)d_in[6];
    const float* bc     = (const float*)d_in[7];
    const float* gamma  = (const float*)d_in[8];
    const float* beta   = (const float*)d_in[9];
    const float* W_head = (const float*)d_in[10];
    const float* b_head = (const float*)d_in[11];
    float* out = (float*)d_out;

    const int E = in_sizes[1] / 2;
    const int* src = ei;
    const int* dst = ei + E;

    cudaFuncSetAttribute(k_layer, cudaFuncAttributeMaxDynamicSharedMemorySize, SMEM_BYTES);

    // CSR build
    k_zero_csr<<<(NN + 255) / 256, 256>>>();
    k_count<<<(E + 255) / 256, 256>>>(dst, E);
    k_scan<<<1, 1024>>>(E);
    k_fill<<<(E + 255) / 256, 256>>>(src, dst, E);

    // Wc transpose + hi/lo bf16 split
    k_transB<<<(3 * KTOT * HH) / 256, 256>>>(Wc);

    // input layer: h = relu(x @ W_in + b_in)
    k_gemm_in<<<NN / 128, 256>>>(x, W_in, b_in);

    for (int l = 0; l < 3; l++) {
        k_layer<<<NN / 128, 256, SMEM_BYTES>>>(
            cen + l * RR * HH, wid + l * RR * HH, bc + l * RR * HH, l);
        k_aggregate<<<NN / 8, 256>>>();
        k_zero_stats<<<1, 128>>>();
        k_bn_stats<<<512, 128>>>();
        k_bn_apply<<<2048, 128>>>(gamma + l * HH, beta + l * HH);
    }

    k_head<<<NN, 128>>>(W_head, b_head, out);
}